// round 11
// baseline (speedup 1.0000x reference)
#include <cuda_runtime.h>
#include <cuda_bf16.h>
#include <math.h>
#include <stdint.h>

#define T_DIM 512
#define B_DIM 64
#define IC 512
#define HC 512
#define L_DIM 2
#define K1 1024      // IC + HC (weight row stride)
#define N1 1024      // 2 * HC
#define NB 128       // serial blocks (1 CTA/SM, co-resident)
#define NT 512       // serial threads per block (16 warps)

#define M_ALL (T_DIM * B_DIM)          // 32768
#define N_ALL (N1 + HC)                // 1536

#define OUT_ACT ((size_t)T_DIM * B_DIM * HC)

// ---------------- device-global scratch (allocation-free rule) ----------------
__device__ float g_act [(size_t)T_DIM * B_DIM * HC];
__device__ float g_pre1[(size_t)T_DIM * B_DIM * N1];
__device__ float g_pre2[(size_t)T_DIM * B_DIM * HC];
__device__ float g_h [B_DIM * HC];
__device__ float g_rh[B_DIM * HC];
__device__ float g_z [B_DIM * HC];
__device__ __nv_bfloat16 g_ahi[(size_t)M_ALL * IC];
__device__ __nv_bfloat16 g_alo[(size_t)M_ALL * IC];
__device__ __nv_bfloat16 g_whi[(size_t)N_ALL * IC];
__device__ __nv_bfloat16 g_wlo[(size_t)N_ALL * IC];
__device__ unsigned g_arrive[NB];      // packed: one warp-coalesced read covers 32
__device__ unsigned g_bar_gen = 0;     // broadcast epoch
__device__ unsigned g_dead    = 0;

__device__ __forceinline__ unsigned ld_u32_cg(const unsigned* p) {
    unsigned v;
    asm volatile("ld.global.cg.u32 %0, [%1];" : "=r"(v) : "l"(p) : "memory");
    return v;
}
__device__ __forceinline__ unsigned ld_acq(const unsigned* p) {
    unsigned v;
    asm volatile("ld.acquire.gpu.u32 %0, [%1];" : "=r"(v) : "l"(p) : "memory");
    return v;
}
__device__ __forceinline__ void st_rel(unsigned* p, unsigned v) {
    asm volatile("st.release.gpu.u32 [%0], %1;" :: "l"(p), "r"(v) : "memory");
}

// Grid barrier v2: contention-free. Arrivals = one st.release per CTA to its
// OWN slot (no RMW). Detector = warp 0 of CTA 0 polls all 128 slots with 4
// coalesced ld.acquire + __all_sync, then releases the broadcast epoch.
// bar.sync chains intra-CTA happens-before into the release store; acquire
// loads order the consumer side. Bounded spin -> terminating wrong answer.
__device__ __forceinline__ void grid_bar(unsigned target) {
    __syncthreads();
    const int bid = blockIdx.x;
    if (bid == 0) {
        if (threadIdx.x < 32) {
            if (ld_u32_cg(&g_dead) == 0u) {
                if (threadIdx.x == 0) st_rel(&g_arrive[0], target);
                int it = 0;
                for (;;) {
                    unsigned v0 = ld_acq(&g_arrive[threadIdx.x]);
                    unsigned v1 = ld_acq(&g_arrive[threadIdx.x + 32]);
                    unsigned v2 = ld_acq(&g_arrive[threadIdx.x + 64]);
                    unsigned v3 = ld_acq(&g_arrive[threadIdx.x + 96]);
                    bool ok = ((int)(v0 - target) >= 0) && ((int)(v1 - target) >= 0)
                           && ((int)(v2 - target) >= 0) && ((int)(v3 - target) >= 0);
                    if (__all_sync(0xffffffffu, ok)) break;
                    if (++it > (1 << 17)) {
                        if (threadIdx.x == 0) st_rel(&g_dead, 1u);
                        break;
                    }
                }
            }
            if (threadIdx.x == 0) st_rel(&g_bar_gen, target);  // release even if dead
        }
    } else if (threadIdx.x == 0) {
        if (ld_u32_cg(&g_dead) == 0u) {
            st_rel(&g_arrive[bid], target);
            int it = 0;
            while ((int)(ld_acq(&g_bar_gen) - target) < 0) {
                if (++it > (1 << 18)) { st_rel(&g_dead, 1u); break; }
            }
        }
    }
    __syncthreads();
}

// ---------------- fp32 -> (bf16 hi, bf16 lo) split ----------------
__device__ __forceinline__ void split4(float4 v, uint2& hi, uint2& lo) {
    __nv_bfloat16 h0 = __float2bfloat16_rn(v.x);
    __nv_bfloat16 h1 = __float2bfloat16_rn(v.y);
    __nv_bfloat16 h2 = __float2bfloat16_rn(v.z);
    __nv_bfloat16 h3 = __float2bfloat16_rn(v.w);
    __nv_bfloat16 l0 = __float2bfloat16_rn(v.x - __bfloat162float(h0));
    __nv_bfloat16 l1 = __float2bfloat16_rn(v.y - __bfloat162float(h1));
    __nv_bfloat16 l2 = __float2bfloat16_rn(v.z - __bfloat162float(h2));
    __nv_bfloat16 l3 = __float2bfloat16_rn(v.w - __bfloat162float(h3));
    hi.x = (unsigned)__bfloat16_as_ushort(h0) | ((unsigned)__bfloat16_as_ushort(h1) << 16);
    hi.y = (unsigned)__bfloat16_as_ushort(h2) | ((unsigned)__bfloat16_as_ushort(h3) << 16);
    lo.x = (unsigned)__bfloat16_as_ushort(l0) | ((unsigned)__bfloat16_as_ushort(l1) << 16);
    lo.y = (unsigned)__bfloat16_as_ushort(l2) | ((unsigned)__bfloat16_as_ushort(l3) << 16);
}

__global__ void __launch_bounds__(256)
conv_act(const float* __restrict__ x, int l)
{
    const float* lin = (l == 0) ? x : g_act;
    size_t i = (size_t)blockIdx.x * 256 + threadIdx.x;
    float4 v = ((const float4*)lin)[i];
    uint2 hi, lo;
    split4(v, hi, lo);
    ((uint2*)g_ahi)[i] = hi;
    ((uint2*)g_alo)[i] = lo;
}

__global__ void __launch_bounds__(256)
conv_w(const float* __restrict__ W1, const float* __restrict__ W2, int l)
{
    size_t i = (size_t)blockIdx.x * 256 + threadIdx.x;
    int n  = (int)(i >> 7);
    int k4 = (int)(i & 127);
    const float* src = (n < N1)
        ? (W1 + (size_t)l * N1 * K1 + (size_t)n * K1 + k4 * 4)
        : (W2 + (size_t)l * HC * K1 + (size_t)(n - N1) * K1 + k4 * 4);
    float4 v = *(const float4*)src;
    uint2 hi, lo;
    split4(v, hi, lo);
    ((uint2*)g_whi)[(size_t)n * 128 + k4] = hi;
    ((uint2*)g_wlo)[(size_t)n * 128 + k4] = lo;
}

// =====================================================================
// mma hoist (unchanged, proven): bf16 two-term split tensor GEMM.
// =====================================================================
#define MBM 128
#define MBN 64
#define MBK 32
#define SAPAD 40

__device__ __forceinline__ void mma16816(float* c, const unsigned* a, const unsigned* b) {
    asm volatile(
        "mma.sync.aligned.m16n8k16.row.col.f32.bf16.bf16.f32 "
        "{%0,%1,%2,%3}, {%4,%5,%6,%7}, {%8,%9}, {%0,%1,%2,%3};\n"
        : "+f"(c[0]), "+f"(c[1]), "+f"(c[2]), "+f"(c[3])
        : "r"(a[0]), "r"(a[1]), "r"(a[2]), "r"(a[3]), "r"(b[0]), "r"(b[1]));
}

__global__ void __launch_bounds__(256)
mma_hoist(const float* __restrict__ b1, const float* __restrict__ b2, int l)
{
    __shared__ __nv_bfloat16 sA[2][MBM][SAPAD];
    __shared__ __nv_bfloat16 sB[2][MBN][SAPAD];

    const int bn  = blockIdx.x;
    const int m0  = blockIdx.y * MBM;
    const int tid = threadIdx.x;
    const int wid = tid >> 5, lane = tid & 31;
    const int wm  = wid & 3;
    const int wn  = wid >> 2;

    float* outp;  const float* bp;  int nstr, n0, wrow0;
    if (bn < 16) { n0 = bn * MBN;        wrow0 = n0;       outp = g_pre1; nstr = N1; bp = b1 + l * N1 + n0; }
    else         { n0 = (bn - 16) * MBN; wrow0 = N1 + n0;  outp = g_pre2; nstr = HC; bp = b2 + l * HC + n0; }

    const __nv_bfloat16* segA[3] = { g_ahi, g_ahi, g_alo };
    const __nv_bfloat16* segW[3] = { g_whi, g_wlo, g_whi };

    const int ar = tid >> 2;
    const int aq = (tid & 3) * 8;

    float acc[2][4][4];
    #pragma unroll
    for (int mt = 0; mt < 2; ++mt)
        #pragma unroll
        for (int nt = 0; nt < 4; ++nt)
            #pragma unroll
            for (int q = 0; q < 4; ++q) acc[mt][nt][q] = 0.f;

    {
        const __nv_bfloat16* A = segA[0];
        const __nv_bfloat16* W = segW[0];
        uint4 a0 = *(const uint4*)(A + (size_t)(m0 + ar) * IC + aq);
        uint4 a1 = *(const uint4*)(A + (size_t)(m0 + ar + 64) * IC + aq);
        uint4 w0 = *(const uint4*)(W + (size_t)(wrow0 + ar) * IC + aq);
        *(uint4*)&sA[0][ar][aq]      = a0;
        *(uint4*)&sA[0][ar + 64][aq] = a1;
        *(uint4*)&sB[0][ar][aq]      = w0;
    }
    __syncthreads();

    const int NIT = 48;
    for (int it = 0; it < NIT; ++it) {
        const int cur = it & 1;
        const bool more = (it + 1) < NIT;
        uint4 na0, na1, nw0;
        if (more) {
            int seg = (it + 1) >> 4;
            int kt  = ((it + 1) & 15) * MBK;
            const __nv_bfloat16* A = segA[seg];
            const __nv_bfloat16* W = segW[seg];
            na0 = *(const uint4*)(A + (size_t)(m0 + ar) * IC + kt + aq);
            na1 = *(const uint4*)(A + (size_t)(m0 + ar + 64) * IC + kt + aq);
            nw0 = *(const uint4*)(W + (size_t)(wrow0 + ar) * IC + kt + aq);
        }

        #pragma unroll
        for (int ks = 0; ks < MBK; ks += 16) {
            const int kb = ks + (lane & 3) * 2;
            unsigned af[2][4], bf[4][2];
            #pragma unroll
            for (int mt = 0; mt < 2; ++mt) {
                int r = wm * 32 + mt * 16 + (lane >> 2);
                af[mt][0] = *(const unsigned*)&sA[cur][r][kb];
                af[mt][1] = *(const unsigned*)&sA[cur][r + 8][kb];
                af[mt][2] = *(const unsigned*)&sA[cur][r][kb + 8];
                af[mt][3] = *(const unsigned*)&sA[cur][r + 8][kb + 8];
            }
            #pragma unroll
            for (int nt = 0; nt < 4; ++nt) {
                int c = wn * 32 + nt * 8 + (lane >> 2);
                bf[nt][0] = *(const unsigned*)&sB[cur][c][kb];
                bf[nt][1] = *(const unsigned*)&sB[cur][c][kb + 8];
            }
            #pragma unroll
            for (int mt = 0; mt < 2; ++mt)
                #pragma unroll
                for (int nt = 0; nt < 4; ++nt)
                    mma16816(acc[mt][nt], af[mt], bf[nt]);
        }

        if (more) {
            const int nxt = cur ^ 1;
            *(uint4*)&sA[nxt][ar][aq]      = na0;
            *(uint4*)&sA[nxt][ar + 64][aq] = na1;
            *(uint4*)&sB[nxt][ar][aq]      = nw0;
            __syncthreads();
        }
    }

    #pragma unroll
    for (int mt = 0; mt < 2; ++mt) {
        #pragma unroll
        for (int nt = 0; nt < 4; ++nt) {
            int r  = m0 + wm * 32 + mt * 16 + (lane >> 2);
            int cl = wn * 32 + nt * 8 + (lane & 3) * 2;
            float bx = bp[cl], by = bp[cl + 1];
            float2 o0 = { acc[mt][nt][0] + bx, acc[mt][nt][1] + by };
            float2 o1 = { acc[mt][nt][2] + bx, acc[mt][nt][3] + by };
            *(float2*)(outp + (size_t)r * nstr + n0 + cl)       = o0;
            *(float2*)(outp + (size_t)(r + 8) * nstr + n0 + cl) = o1;
        }
    }
}

// =====================================================================
// Serial kernel: byte-identical compute/partitioning to round 10;
// ONLY the grid barrier implementation changed (see grid_bar above).
// =====================================================================
#define WS 520      // smem row stride in halfs (bank-conflict-free frags)
#define OFF_W1H 0
#define OFF_W1L 33280
#define OFF_W2H 66560
#define OFF_W2L 99840
#define OFF_HH  133120
#define OFF_HL  149760
#define OFF_RED 166400
#define SER_SMEM_BYTES 182784

__global__ void __launch_bounds__(NT, 1)
serial_kernel(const float* __restrict__ hiddens,
              const float* __restrict__ W1, const float* __restrict__ W2,
              float* __restrict__ out, int l)
{
    extern __shared__ char smc[];
    __nv_bfloat16* sW1h = (__nv_bfloat16*)(smc + OFF_W1H);
    __nv_bfloat16* sW1l = (__nv_bfloat16*)(smc + OFF_W1L);
    __nv_bfloat16* sW2h = (__nv_bfloat16*)(smc + OFF_W2H);
    __nv_bfloat16* sW2l = (__nv_bfloat16*)(smc + OFF_W2L);
    __nv_bfloat16* sHh  = (__nv_bfloat16*)(smc + OFF_HH);
    __nv_bfloat16* sHl  = (__nv_bfloat16*)(smc + OFF_HL);
    float*         red  = (float*)(smc + OFF_RED);   // [ks 8][jt 4][lane 32][4]

    const int tid  = threadIdx.x;
    const int bid  = blockIdx.x;
    const int wp   = tid >> 5;
    const int lane = tid & 31;

    const int jg1 = bid >> 2;   // 0..31
    const int bg1 = bid & 3;    // 0..3
    const int jg2 = bid >> 3;   // 0..15
    const int bg2 = bid & 7;    // 0..7

    float* lout = (l == 0) ? g_act : out;

    const int jl1 = tid & 31, bl1 = tid >> 5;           // phase1: 32j x 16b
    const int j1  = jg1 * 32 + jl1;
    const int b1o = bg1 * 16 + bl1;
    const int jl2 = tid & 31, bl2 = (tid >> 5) & 7;     // phase2: 32j x 8b
    const int j2  = jg2 * 32 + jl2;
    const int b2o = bg2 * 8 + bl2;
    const bool p2own = (tid < 256);

    const int lf1 = (bl1 & 7) * 4 + ((jl1 & 7) >> 1);
    const int cc1 = (jl1 & 1) + ((bl1 >> 3) << 1);
    const int jt1 = jl1 >> 3;
    const int lf2 = bl2 * 4 + ((jl2 & 7) >> 1);
    const int cc2 = jl2 & 1;
    const int jt2 = jl2 >> 3;

    // ---- stage bf16-split weights once per layer ----
    for (int idx = tid; idx < 32 * 128; idx += NT) {    // idx over float4
        int jl = idx >> 7, k4 = idx & 127;
        float4 v1 = *(const float4*)&W1[((size_t)l * N1 + jg1 * 32 + jl) * K1 + IC + k4 * 4];
        float4 v2 = *(const float4*)&W2[((size_t)l * HC + jg2 * 32 + jl) * K1 + IC + k4 * 4];
        uint2 hi, lo;
        split4(v1, hi, lo);
        *(uint2*)&sW1h[jl * WS + k4 * 4] = hi;
        *(uint2*)&sW1l[jl * WS + k4 * 4] = lo;
        split4(v2, hi, lo);
        *(uint2*)&sW2h[jl * WS + k4 * 4] = hi;
        *(uint2*)&sW2l[jl * WS + k4 * 4] = lo;
    }

    // Init hidden state
    { int i = bid * NT + tid;
      if (i < B_DIM * HC) g_h[i] = hiddens[l * HC + (i & (HC - 1))]; }

    unsigned ep = ld_acq(&g_bar_gen);
    grid_bar(++ep);

    const float4* gh4  = (const float4*)g_h;
    const float4* grh4 = (const float4*)g_rh;

    const int frow = lane >> 2;          // fragment row 0..7
    const int fkq  = (lane & 3) * 2;     // fragment k offset

    for (int t = 0; t < T_DIM; ++t) {
        float pre1v = __ldcg(&g_pre1[((size_t)t * B_DIM + b1o) * N1 + j1]);
        float hv = 0.f;
        if (jg1 < 16) hv = __ldcg(&g_h[b1o * HC + j1]);
        float pre2v = 0.f, hov = 0.f;
        if (p2own) {
            pre2v = __ldcg(&g_pre2[((size_t)t * B_DIM + b2o) * HC + j2]);
            hov   = __ldcg(&g_h[b2o * HC + j2]);
        }

        // ---- stage h[bg1*16 .. +16][:] as bf16 hi/lo (2048 float4) ----
        #pragma unroll
        for (int q = 0; q < 4; ++q) {
            int i4 = q * NT + tid;
            int row = i4 >> 7, c4 = i4 & 127;
            float4 v = __ldcg(&gh4[(size_t)bg1 * 2048 + i4]);
            uint2 hi, lo;
            split4(v, hi, lo);
            *(uint2*)&sHh[row * WS + c4 * 4] = hi;
            *(uint2*)&sHl[row * WS + c4 * 4] = lo;
        }
        __syncthreads();

        // ---- Phase 1 compute: h @ W1h^T on tensor cores ----
        {
            const int ks = wp >> 1;
            const int jp = wp & 1;
            float acc[2][4];
            #pragma unroll
            for (int jj = 0; jj < 2; ++jj)
                #pragma unroll
                for (int q = 0; q < 4; ++q) acc[jj][q] = 0.f;
            #pragma unroll
            for (int cc = 0; cc < 4; ++cc) {
                int kb = ks * 64 + cc * 16 + fkq;
                unsigned ah[4], al[4];
                ah[0] = *(const unsigned*)&sHh[frow * WS + kb];
                ah[1] = *(const unsigned*)&sHh[(frow + 8) * WS + kb];
                ah[2] = *(const unsigned*)&sHh[frow * WS + kb + 8];
                ah[3] = *(const unsigned*)&sHh[(frow + 8) * WS + kb + 8];
                al[0] = *(const unsigned*)&sHl[frow * WS + kb];
                al[1] = *(const unsigned*)&sHl[(frow + 8) * WS + kb];
                al[2] = *(const unsigned*)&sHl[frow * WS + kb + 8];
                al[3] = *(const unsigned*)&sHl[(frow + 8) * WS + kb + 8];
                #pragma unroll
                for (int jj = 0; jj < 2; ++jj) {
                    int jr = (jp * 2 + jj) * 8 + frow;
                    unsigned bh[2], bl_[2];
                    bh[0]  = *(const unsigned*)&sW1h[jr * WS + kb];
                    bh[1]  = *(const unsigned*)&sW1h[jr * WS + kb + 8];
                    bl_[0] = *(const unsigned*)&sW1l[jr * WS + kb];
                    bl_[1] = *(const unsigned*)&sW1l[jr * WS + kb + 8];
                    mma16816(acc[jj], ah, bh);
                    mma16816(acc[jj], ah, bl_);
                    mma16816(acc[jj], al, bh);
                }
            }
            #pragma unroll
            for (int jj = 0; jj < 2; ++jj)
                *(float4*)&red[((ks * 4 + jp * 2 + jj) * 32 + lane) * 4] =
                    *(float4*)acc[jj];
        }
        __syncthreads();

        // ---- Phase 1 epilogue ----
        {
            float s = 0.f;
            #pragma unroll
            for (int ks = 0; ks < 8; ++ks)
                s += red[((ks * 4 + jt1) * 32 + lf1) * 4 + cc1];
            float pre = s + pre1v;
            float sg  = __fdividef(1.f, 1.f + __expf(-pre));
            if (jg1 < 16) g_rh[b1o * HC + j1] = sg * hv;
            else          g_z[b1o * HC + (j1 - HC)] = sg;
        }
        grid_bar(++ep);

        // ---- stage rh[bg2*8 .. +8][:]; prefetch z ----
        float zv = 0.f;
        if (p2own) zv = __ldcg(&g_z[b2o * HC + j2]);
        #pragma unroll
        for (int q = 0; q < 2; ++q) {
            int i4 = q * NT + tid;
            int row = i4 >> 7, c4 = i4 & 127;
            float4 v = __ldcg(&grh4[(size_t)bg2 * 1024 + i4]);
            uint2 hi, lo;
            split4(v, hi, lo);
            *(uint2*)&sHh[row * WS + c4 * 4] = hi;
            *(uint2*)&sHl[row * WS + c4 * 4] = lo;
        }
        __syncthreads();

        // ---- Phase 2 compute ----
        {
            const int ks = wp >> 1;
            const int jp = wp & 1;
            float acc[2][4];
            #pragma unroll
            for (int jj = 0; jj < 2; ++jj)
                #pragma unroll
                for (int q = 0; q < 4; ++q) acc[jj][q] = 0.f;
            #pragma unroll
            for (int cc = 0; cc < 4; ++cc) {
                int kb = ks * 64 + cc * 16 + fkq;
                unsigned ah[4], al[4];
                ah[0] = *(const unsigned*)&sHh[frow * WS + kb];
                ah[1] = *(const unsigned*)&sHh[(frow + 8) * WS + kb];
                ah[2] = *(const unsigned*)&sHh[frow * WS + kb + 8];
                ah[3] = *(const unsigned*)&sHh[(frow + 8) * WS + kb + 8];
                al[0] = *(const unsigned*)&sHl[frow * WS + kb];
                al[1] = *(const unsigned*)&sHl[(frow + 8) * WS + kb];
                al[2] = *(const unsigned*)&sHl[frow * WS + kb + 8];
                al[3] = *(const unsigned*)&sHl[(frow + 8) * WS + kb + 8];
                #pragma unroll
                for (int jj = 0; jj < 2; ++jj) {
                    int jr = (jp * 2 + jj) * 8 + frow;
                    unsigned bh[2], bl_[2];
                    bh[0]  = *(const unsigned*)&sW2h[jr * WS + kb];
                    bh[1]  = *(const unsigned*)&sW2h[jr * WS + kb + 8];
                    bl_[0] = *(const unsigned*)&sW2l[jr * WS + kb];
                    bl_[1] = *(const unsigned*)&sW2l[jr * WS + kb + 8];
                    mma16816(acc[jj], ah, bh);
                    mma16816(acc[jj], ah, bl_);
                    mma16816(acc[jj], al, bh);
                }
            }
            #pragma unroll
            for (int jj = 0; jj < 2; ++jj)
                *(float4*)&red[((ks * 4 + jp * 2 + jj) * 32 + lane) * 4] =
                    *(float4*)acc[jj];
        }
        __syncthreads();

        // ---- Phase 2 epilogue ----
        if (p2own) {
            float s = 0.f;
            #pragma unroll
            for (int ks = 0; ks < 8; ++ks)
                s += red[((ks * 4 + jt2) * 32 + lf2) * 4 + cc2];
            float x2v = s + pre2v;
            float gg  = 1.f - __fdividef(2.f, __expf(2.f * x2v) + 1.f);
            float hn  = zv * hov + (1.f - zv) * gg;
            g_h[b2o * HC + j2] = hn;
            lout[((size_t)t * B_DIM + b2o) * HC + j2] = hn;
            if (t == T_DIM - 1)
                out[OUT_ACT + (size_t)l * B_DIM * HC + b2o * HC + j2] = hn;
        }
        grid_bar(++ep);
    }
}

extern "C" void kernel_launch(void* const* d_in, const int* in_sizes, int n_in,
                              void* d_out, int out_size) {
    const float* x       = (const float*)d_in[0];
    const float* hiddens = (const float*)d_in[1];
    const float* W1      = (const float*)d_in[2];
    const float* b1      = (const float*)d_in[3];
    const float* W2      = (const float*)d_in[4];
    const float* b2      = (const float*)d_in[5];
    float* out = (float*)d_out;

    cudaFuncSetAttribute(serial_kernel,
                         cudaFuncAttributeMaxDynamicSharedMemorySize,
                         SER_SMEM_BYTES);

    for (int l = 0; l < L_DIM; ++l) {
        conv_act<<<M_ALL * IC / 4 / 256, 256>>>(x, l);
        conv_w  <<<N_ALL * IC / 4 / 256, 256>>>(W1, W2, l);
        mma_hoist<<<dim3(24, M_ALL / MBM), 256>>>(b1, b2, l);
        serial_kernel<<<NB, NT, SER_SMEM_BYTES>>>(hiddens, W1, W2, out, l);
    }
}

// round 12
// speedup vs baseline: 1.0353x; 1.0353x over previous
#include <cuda_runtime.h>
#include <cuda_bf16.h>
#include <math.h>
#include <stdint.h>

#define T_DIM 512
#define B_DIM 64
#define IC 512
#define HC 512
#define L_DIM 2
#define K1 1024      // IC + HC (weight row stride)
#define N1 1024      // 2 * HC
#define NB 128       // serial blocks (1 CTA/SM, co-resident)
#define NT 512       // serial threads per block (16 warps)

#define M_ALL (T_DIM * B_DIM)          // 32768
#define N_ALL (N1 + HC)                // 1536

#define OUT_ACT ((size_t)T_DIM * B_DIM * HC)

// ---------------- device-global scratch (allocation-free rule) ----------------
__device__ float g_act [(size_t)T_DIM * B_DIM * HC];
__device__ float g_pre1[(size_t)T_DIM * B_DIM * N1];
__device__ float g_pre2[(size_t)T_DIM * B_DIM * HC];
__device__ float g_h [B_DIM * HC];
__device__ float g_z [B_DIM * HC];
__device__ __nv_bfloat16 g_hh [B_DIM * HC];   // h  split hi
__device__ __nv_bfloat16 g_hl [B_DIM * HC];   // h  split lo
__device__ __nv_bfloat16 g_rhh[B_DIM * HC];   // rh split hi
__device__ __nv_bfloat16 g_rhl[B_DIM * HC];   // rh split lo
__device__ __nv_bfloat16 g_ahi[(size_t)M_ALL * IC];
__device__ __nv_bfloat16 g_alo[(size_t)M_ALL * IC];
__device__ __nv_bfloat16 g_whi[(size_t)N_ALL * IC];
__device__ __nv_bfloat16 g_wlo[(size_t)N_ALL * IC];
__device__ unsigned g_bar_cnt = 0;
__device__ unsigned g_bar_gen = 0;
__device__ unsigned g_dead    = 0;

__device__ __forceinline__ unsigned ld_u32_cg(const unsigned* p) {
    unsigned v;
    asm volatile("ld.global.cg.u32 %0, [%1];" : "=r"(v) : "l"(p) : "memory");
    return v;
}

// Grid barrier (round-10 proven best): atomic arrivals, epoch release,
// plain-load pollers, bounded spin -> terminating wrong answer, never a
// wedged device.
__device__ __forceinline__ void grid_bar(unsigned target) {
    __syncthreads();
    if (threadIdx.x == 0) {
        if (ld_u32_cg(&g_dead) == 0u) {
            __threadfence();
            unsigned t = atomicAdd(&g_bar_cnt, 1u);
            if (t == NB - 1) {
                g_bar_cnt = 0;
                __threadfence();
                atomicExch(&g_bar_gen, target);
            } else {
                int it = 0;
                while (ld_u32_cg(&g_bar_gen) != target) {
                    if (++it > (1 << 20)) { atomicExch(&g_dead, 1u); break; }
                }
            }
            __threadfence();
        }
    }
    __syncthreads();
}

// ---------------- fp32 -> (bf16 hi, bf16 lo) split ----------------
__device__ __forceinline__ void split4(float4 v, uint2& hi, uint2& lo) {
    __nv_bfloat16 h0 = __float2bfloat16_rn(v.x);
    __nv_bfloat16 h1 = __float2bfloat16_rn(v.y);
    __nv_bfloat16 h2 = __float2bfloat16_rn(v.z);
    __nv_bfloat16 h3 = __float2bfloat16_rn(v.w);
    __nv_bfloat16 l0 = __float2bfloat16_rn(v.x - __bfloat162float(h0));
    __nv_bfloat16 l1 = __float2bfloat16_rn(v.y - __bfloat162float(h1));
    __nv_bfloat16 l2 = __float2bfloat16_rn(v.z - __bfloat162float(h2));
    __nv_bfloat16 l3 = __float2bfloat16_rn(v.w - __bfloat162float(h3));
    hi.x = (unsigned)__bfloat16_as_ushort(h0) | ((unsigned)__bfloat16_as_ushort(h1) << 16);
    hi.y = (unsigned)__bfloat16_as_ushort(h2) | ((unsigned)__bfloat16_as_ushort(h3) << 16);
    lo.x = (unsigned)__bfloat16_as_ushort(l0) | ((unsigned)__bfloat16_as_ushort(l1) << 16);
    lo.y = (unsigned)__bfloat16_as_ushort(l2) | ((unsigned)__bfloat16_as_ushort(l3) << 16);
}

__device__ __forceinline__ void split1(float v, __nv_bfloat16& hi, __nv_bfloat16& lo) {
    hi = __float2bfloat16_rn(v);
    lo = __float2bfloat16_rn(v - __bfloat162float(hi));
}

__global__ void __launch_bounds__(256)
conv_act(const float* __restrict__ x, int l)
{
    const float* lin = (l == 0) ? x : g_act;
    size_t i = (size_t)blockIdx.x * 256 + threadIdx.x;
    float4 v = ((const float4*)lin)[i];
    uint2 hi, lo;
    split4(v, hi, lo);
    ((uint2*)g_ahi)[i] = hi;
    ((uint2*)g_alo)[i] = lo;
}

__global__ void __launch_bounds__(256)
conv_w(const float* __restrict__ W1, const float* __restrict__ W2, int l)
{
    size_t i = (size_t)blockIdx.x * 256 + threadIdx.x;
    int n  = (int)(i >> 7);
    int k4 = (int)(i & 127);
    const float* src = (n < N1)
        ? (W1 + (size_t)l * N1 * K1 + (size_t)n * K1 + k4 * 4)
        : (W2 + (size_t)l * HC * K1 + (size_t)(n - N1) * K1 + k4 * 4);
    float4 v = *(const float4*)src;
    uint2 hi, lo;
    split4(v, hi, lo);
    ((uint2*)g_whi)[(size_t)n * 128 + k4] = hi;
    ((uint2*)g_wlo)[(size_t)n * 128 + k4] = lo;
}

// =====================================================================
// mma hoist (unchanged, proven): bf16 two-term split tensor GEMM.
// =====================================================================
#define MBM 128
#define MBN 64
#define MBK 32
#define SAPAD 40

__device__ __forceinline__ void mma16816(float* c, const unsigned* a, const unsigned* b) {
    asm volatile(
        "mma.sync.aligned.m16n8k16.row.col.f32.bf16.bf16.f32 "
        "{%0,%1,%2,%3}, {%4,%5,%6,%7}, {%8,%9}, {%0,%1,%2,%3};\n"
        : "+f"(c[0]), "+f"(c[1]), "+f"(c[2]), "+f"(c[3])
        : "r"(a[0]), "r"(a[1]), "r"(a[2]), "r"(a[3]), "r"(b[0]), "r"(b[1]));
}

__global__ void __launch_bounds__(256)
mma_hoist(const float* __restrict__ b1, const float* __restrict__ b2, int l)
{
    __shared__ __nv_bfloat16 sA[2][MBM][SAPAD];
    __shared__ __nv_bfloat16 sB[2][MBN][SAPAD];

    const int bn  = blockIdx.x;
    const int m0  = blockIdx.y * MBM;
    const int tid = threadIdx.x;
    const int wid = tid >> 5, lane = tid & 31;
    const int wm  = wid & 3;
    const int wn  = wid >> 2;

    float* outp;  const float* bp;  int nstr, n0, wrow0;
    if (bn < 16) { n0 = bn * MBN;        wrow0 = n0;       outp = g_pre1; nstr = N1; bp = b1 + l * N1 + n0; }
    else         { n0 = (bn - 16) * MBN; wrow0 = N1 + n0;  outp = g_pre2; nstr = HC; bp = b2 + l * HC + n0; }

    const __nv_bfloat16* segA[3] = { g_ahi, g_ahi, g_alo };
    const __nv_bfloat16* segW[3] = { g_whi, g_wlo, g_whi };

    const int ar = tid >> 2;
    const int aq = (tid & 3) * 8;

    float acc[2][4][4];
    #pragma unroll
    for (int mt = 0; mt < 2; ++mt)
        #pragma unroll
        for (int nt = 0; nt < 4; ++nt)
            #pragma unroll
            for (int q = 0; q < 4; ++q) acc[mt][nt][q] = 0.f;

    {
        const __nv_bfloat16* A = segA[0];
        const __nv_bfloat16* W = segW[0];
        uint4 a0 = *(const uint4*)(A + (size_t)(m0 + ar) * IC + aq);
        uint4 a1 = *(const uint4*)(A + (size_t)(m0 + ar + 64) * IC + aq);
        uint4 w0 = *(const uint4*)(W + (size_t)(wrow0 + ar) * IC + aq);
        *(uint4*)&sA[0][ar][aq]      = a0;
        *(uint4*)&sA[0][ar + 64][aq] = a1;
        *(uint4*)&sB[0][ar][aq]      = w0;
    }
    __syncthreads();

    const int NIT = 48;
    for (int it = 0; it < NIT; ++it) {
        const int cur = it & 1;
        const bool more = (it + 1) < NIT;
        uint4 na0, na1, nw0;
        if (more) {
            int seg = (it + 1) >> 4;
            int kt  = ((it + 1) & 15) * MBK;
            const __nv_bfloat16* A = segA[seg];
            const __nv_bfloat16* W = segW[seg];
            na0 = *(const uint4*)(A + (size_t)(m0 + ar) * IC + kt + aq);
            na1 = *(const uint4*)(A + (size_t)(m0 + ar + 64) * IC + kt + aq);
            nw0 = *(const uint4*)(W + (size_t)(wrow0 + ar) * IC + kt + aq);
        }

        #pragma unroll
        for (int ks = 0; ks < MBK; ks += 16) {
            const int kb = ks + (lane & 3) * 2;
            unsigned af[2][4], bf[4][2];
            #pragma unroll
            for (int mt = 0; mt < 2; ++mt) {
                int r = wm * 32 + mt * 16 + (lane >> 2);
                af[mt][0] = *(const unsigned*)&sA[cur][r][kb];
                af[mt][1] = *(const unsigned*)&sA[cur][r + 8][kb];
                af[mt][2] = *(const unsigned*)&sA[cur][r][kb + 8];
                af[mt][3] = *(const unsigned*)&sA[cur][r + 8][kb + 8];
            }
            #pragma unroll
            for (int nt = 0; nt < 4; ++nt) {
                int c = wn * 32 + nt * 8 + (lane >> 2);
                bf[nt][0] = *(const unsigned*)&sB[cur][c][kb];
                bf[nt][1] = *(const unsigned*)&sB[cur][c][kb + 8];
            }
            #pragma unroll
            for (int mt = 0; mt < 2; ++mt)
                #pragma unroll
                for (int nt = 0; nt < 4; ++nt)
                    mma16816(acc[mt][nt], af[mt], bf[nt]);
        }

        if (more) {
            const int nxt = cur ^ 1;
            *(uint4*)&sA[nxt][ar][aq]      = na0;
            *(uint4*)&sA[nxt][ar + 64][aq] = na1;
            *(uint4*)&sB[nxt][ar][aq]      = nw0;
            __syncthreads();
        }
    }

    #pragma unroll
    for (int mt = 0; mt < 2; ++mt) {
        #pragma unroll
        for (int nt = 0; nt < 4; ++nt) {
            int r  = m0 + wm * 32 + mt * 16 + (lane >> 2);
            int cl = wn * 32 + nt * 8 + (lane & 3) * 2;
            float bx = bp[cl], by = bp[cl + 1];
            float2 o0 = { acc[mt][nt][0] + bx, acc[mt][nt][1] + by };
            float2 o1 = { acc[mt][nt][2] + bx, acc[mt][nt][3] + by };
            *(float2*)(outp + (size_t)r * nstr + n0 + cl)       = o0;
            *(float2*)(outp + (size_t)(r + 8) * nstr + n0 + cl) = o1;
        }
    }
}

// =====================================================================
// Serial kernel: round-10 skeleton + round-10 barrier. Changes:
//  (1) fragment loads via ldmatrix.x4 (16 LDSM vs 64 LDS.32 per warp/phase)
//  (2) h / rh exchanged pre-split (bf16 hi/lo) in global; staging = raw copy
// =====================================================================
#define WS 520      // smem row stride in halfs
#define OFF_W1H 0
#define OFF_W1L 33280
#define OFF_W2H 66560
#define OFF_W2L 99840
#define OFF_HH  133120
#define OFF_HL  149760
#define OFF_RED 166400
#define SER_SMEM_BYTES 182784

__device__ __forceinline__ uint32_t s2u(const void* p) {
    return (uint32_t)__cvta_generic_to_shared(p);
}
__device__ __forceinline__ void ldsm_x4(unsigned* r, uint32_t addr) {
    asm volatile("ldmatrix.sync.aligned.m8n8.x4.shared.b16 {%0,%1,%2,%3}, [%4];"
                 : "=r"(r[0]), "=r"(r[1]), "=r"(r[2]), "=r"(r[3]) : "r"(addr));
}

__global__ void __launch_bounds__(NT, 1)
serial_kernel(const float* __restrict__ hiddens,
              const float* __restrict__ W1, const float* __restrict__ W2,
              float* __restrict__ out, int l)
{
    extern __shared__ char smc[];
    __nv_bfloat16* sW1h = (__nv_bfloat16*)(smc + OFF_W1H);
    __nv_bfloat16* sW1l = (__nv_bfloat16*)(smc + OFF_W1L);
    __nv_bfloat16* sW2h = (__nv_bfloat16*)(smc + OFF_W2H);
    __nv_bfloat16* sW2l = (__nv_bfloat16*)(smc + OFF_W2L);
    __nv_bfloat16* sHh  = (__nv_bfloat16*)(smc + OFF_HH);
    __nv_bfloat16* sHl  = (__nv_bfloat16*)(smc + OFF_HL);
    float*         red  = (float*)(smc + OFF_RED);   // [ks 8][jt 4][lane 32][4]

    const int tid  = threadIdx.x;
    const int bid  = blockIdx.x;
    const int wp   = tid >> 5;
    const int lane = tid & 31;

    const int jg1 = bid >> 2;   // 0..31
    const int bg1 = bid & 3;    // 0..3
    const int jg2 = bid >> 3;   // 0..15
    const int bg2 = bid & 7;    // 0..7

    float* lout = (l == 0) ? g_act : out;

    const int jl1 = tid & 31, bl1 = tid >> 5;           // phase1: 32j x 16b
    const int j1  = jg1 * 32 + jl1;
    const int b1o = bg1 * 16 + bl1;
    const int jl2 = tid & 31, bl2 = (tid >> 5) & 7;     // phase2: 32j x 8b
    const int j2  = jg2 * 32 + jl2;
    const int b2o = bg2 * 8 + bl2;
    const bool p2own = (tid < 256);

    const int lf1 = (bl1 & 7) * 4 + ((jl1 & 7) >> 1);
    const int cc1 = (jl1 & 1) + ((bl1 >> 3) << 1);
    const int jt1 = jl1 >> 3;
    const int lf2 = bl2 * 4 + ((jl2 & 7) >> 1);
    const int cc2 = jl2 & 1;
    const int jt2 = jl2 >> 3;

    // ---- stage bf16-split weights once per layer ----
    for (int idx = tid; idx < 32 * 128; idx += NT) {    // idx over float4
        int jl = idx >> 7, k4 = idx & 127;
        float4 v1 = *(const float4*)&W1[((size_t)l * N1 + jg1 * 32 + jl) * K1 + IC + k4 * 4];
        float4 v2 = *(const float4*)&W2[((size_t)l * HC + jg2 * 32 + jl) * K1 + IC + k4 * 4];
        uint2 hi, lo;
        split4(v1, hi, lo);
        *(uint2*)&sW1h[jl * WS + k4 * 4] = hi;
        *(uint2*)&sW1l[jl * WS + k4 * 4] = lo;
        split4(v2, hi, lo);
        *(uint2*)&sW2h[jl * WS + k4 * 4] = hi;
        *(uint2*)&sW2l[jl * WS + k4 * 4] = lo;
    }

    // Init hidden state (fp32 + split)
    { int i = bid * NT + tid;
      if (i < B_DIM * HC) {
          float v = hiddens[l * HC + (i & (HC - 1))];
          g_h[i] = v;
          __nv_bfloat16 hi, lo;
          split1(v, hi, lo);
          g_hh[i] = hi;  g_hl[i] = lo;
      } }

    unsigned ep = ld_u32_cg(&g_bar_gen);
    grid_bar(++ep);

    // LDSM lane addressing (same fragment layout as verified scalar loads)
    const int lrow = (lane & 7) + ((lane >> 3) & 1) * 8;   // 0..15
    const int lkof = (lane >> 4) << 3;                     // 0 or 8
    const int frow = lane >> 2;
    const int fkq  = (lane & 3) * 2;

    for (int t = 0; t < T_DIM; ++t) {
        float pre1v = __ldcg(&g_pre1[((size_t)t * B_DIM + b1o) * N1 + j1]);
        float hv = 0.f;
        if (jg1 < 16) hv = __ldcg(&g_h[b1o * HC + j1]);
        float pre2v = 0.f, hov = 0.f;
        if (p2own) {
            pre2v = __ldcg(&g_pre2[((size_t)t * B_DIM + b2o) * HC + j2]);
            hov   = __ldcg(&g_h[b2o * HC + j2]);
        }

        // ---- stage h[bg1*16..+16][:] pre-split: raw uint4 copies ----
        #pragma unroll
        for (int q = 0; q < 2; ++q) {
            int i8 = q * NT + tid;             // over uint4 (8 halfs); 1024 total
            int row = i8 >> 6, c8 = i8 & 63;
            uint4 vh = __ldcg((const uint4*)&g_hh[(size_t)(bg1 * 16 + row) * HC + c8 * 8]);
            uint4 vl = __ldcg((const uint4*)&g_hl[(size_t)(bg1 * 16 + row) * HC + c8 * 8]);
            *(uint4*)&sHh[row * WS + c8 * 8] = vh;
            *(uint4*)&sHl[row * WS + c8 * 8] = vl;
        }
        __syncthreads();

        // ---- Phase 1 compute: h @ W1h^T via LDSM + mma ----
        {
            const int ks = wp >> 1;
            const int jp = wp & 1;
            float acc[2][4];
            #pragma unroll
            for (int jj = 0; jj < 2; ++jj)
                #pragma unroll
                for (int q = 0; q < 4; ++q) acc[jj][q] = 0.f;
            #pragma unroll
            for (int cc = 0; cc < 4; ++cc) {
                int kb0 = ks * 64 + cc * 16 + lkof;
                unsigned ah[4], al[4], wh[4], wl[4];
                ldsm_x4(ah, s2u(&sHh[lrow * WS + kb0]));
                ldsm_x4(al, s2u(&sHl[lrow * WS + kb0]));
                ldsm_x4(wh, s2u(&sW1h[(jp * 16 + lrow) * WS + kb0]));
                ldsm_x4(wl, s2u(&sW1l[(jp * 16 + lrow) * WS + kb0]));
                #pragma unroll
                for (int jj = 0; jj < 2; ++jj) {
                    unsigned bh[2] = { wh[jj], wh[jj + 2] };
                    unsigned bl_[2] = { wl[jj], wl[jj + 2] };
                    mma16816(acc[jj], ah, bh);
                    mma16816(acc[jj], ah, bl_);
                    mma16816(acc[jj], al, bh);
                }
            }
            #pragma unroll
            for (int jj = 0; jj < 2; ++jj)
                *(float4*)&red[((ks * 4 + jp * 2 + jj) * 32 + lane) * 4] =
                    *(float4*)acc[jj];
        }
        __syncthreads();

        // ---- Phase 1 epilogue: r,z; rh written pre-split ----
        {
            float s = 0.f;
            #pragma unroll
            for (int ks = 0; ks < 8; ++ks)
                s += red[((ks * 4 + jt1) * 32 + lf1) * 4 + cc1];
            float pre = s + pre1v;
            float sg  = __fdividef(1.f, 1.f + __expf(-pre));
            if (jg1 < 16) {
                float rhv = sg * hv;
                __nv_bfloat16 hi, lo;
                split1(rhv, hi, lo);
                g_rhh[b1o * HC + j1] = hi;
                g_rhl[b1o * HC + j1] = lo;
            } else {
                g_z[b1o * HC + (j1 - HC)] = sg;
            }
        }
        grid_bar(++ep);

        // ---- stage rh[bg2*8..+8][:] pre-split; prefetch z ----
        float zv = 0.f;
        if (p2own) zv = __ldcg(&g_z[b2o * HC + j2]);
        {
            int i8 = tid;                       // 512 uint4 cover 8 rows
            int row = i8 >> 6, c8 = i8 & 63;
            uint4 vh = __ldcg((const uint4*)&g_rhh[(size_t)(bg2 * 8 + row) * HC + c8 * 8]);
            uint4 vl = __ldcg((const uint4*)&g_rhl[(size_t)(bg2 * 8 + row) * HC + c8 * 8]);
            *(uint4*)&sHh[row * WS + c8 * 8] = vh;
            *(uint4*)&sHl[row * WS + c8 * 8] = vl;
        }
        __syncthreads();

        // ---- Phase 2 compute (rows 8..15 stale/unused, matches R10) ----
        {
            const int ks = wp >> 1;
            const int jp = wp & 1;
            float acc[2][4];
            #pragma unroll
            for (int jj = 0; jj < 2; ++jj)
                #pragma unroll
                for (int q = 0; q < 4; ++q) acc[jj][q] = 0.f;
            #pragma unroll
            for (int cc = 0; cc < 4; ++cc) {
                int kb0 = ks * 64 + cc * 16 + lkof;
                unsigned ah[4], al[4], wh[4], wl[4];
                ldsm_x4(ah, s2u(&sHh[lrow * WS + kb0]));
                ldsm_x4(al, s2u(&sHl[lrow * WS + kb0]));
                ldsm_x4(wh, s2u(&sW2h[(jp * 16 + lrow) * WS + kb0]));
                ldsm_x4(wl, s2u(&sW2l[(jp * 16 + lrow) * WS + kb0]));
                #pragma unroll
                for (int jj = 0; jj < 2; ++jj) {
                    unsigned bh[2] = { wh[jj], wh[jj + 2] };
                    unsigned bl_[2] = { wl[jj], wl[jj + 2] };
                    mma16816(acc[jj], ah, bh);
                    mma16816(acc[jj], ah, bl_);
                    mma16816(acc[jj], al, bh);
                }
            }
            #pragma unroll
            for (int jj = 0; jj < 2; ++jj)
                *(float4*)&red[((ks * 4 + jp * 2 + jj) * 32 + lane) * 4] =
                    *(float4*)acc[jj];
        }
        __syncthreads();

        // ---- Phase 2 epilogue: h update, written fp32 + pre-split ----
        if (p2own) {
            float s = 0.f;
            #pragma unroll
            for (int ks = 0; ks < 8; ++ks)
                s += red[((ks * 4 + jt2) * 32 + lf2) * 4 + cc2];
            float x2v = s + pre2v;
            float gg  = 1.f - __fdividef(2.f, __expf(2.f * x2v) + 1.f);
            float hn  = zv * hov + (1.f - zv) * gg;
            g_h[b2o * HC + j2] = hn;
            __nv_bfloat16 hi, lo;
            split1(hn, hi, lo);
            g_hh[b2o * HC + j2] = hi;
            g_hl[b2o * HC + j2] = lo;
            lout[((size_t)t * B_DIM + b2o) * HC + j2] = hn;
            if (t == T_DIM - 1)
                out[OUT_ACT + (size_t)l * B_DIM * HC + b2o * HC + j2] = hn;
        }
        grid_bar(++ep);
    }
}

extern "C" void kernel_launch(void* const* d_in, const int* in_sizes, int n_in,
                              void* d_out, int out_size) {
    const float* x       = (const float*)d_in[0];
    const float* hiddens = (const float*)d_in[1];
    const float* W1      = (const float*)d_in[2];
    const float* b1      = (const float*)d_in[3];
    const float* W2      = (const float*)d_in[4];
    const float* b2      = (const float*)d_in[5];
    float* out = (float*)d_out;

    cudaFuncSetAttribute(serial_kernel,
                         cudaFuncAttributeMaxDynamicSharedMemorySize,
                         SER_SMEM_BYTES);

    for (int l = 0; l < L_DIM; ++l) {
        conv_act<<<M_ALL * IC / 4 / 256, 256>>>(x, l);
        conv_w  <<<N_ALL * IC / 4 / 256, 256>>>(W1, W2, l);
        mma_hoist<<<dim3(24, M_ALL / MBM), 256>>>(b1, b2, l);
        serial_kernel<<<NB, NT, SER_SMEM_BYTES>>>(hiddens, W1, W2, out, l);
    }
}

// round 13
// speedup vs baseline: 1.1885x; 1.1480x over previous
#include <cuda_runtime.h>
#include <cuda_bf16.h>
#include <math.h>
#include <stdint.h>

#define T_DIM 512
#define B_DIM 64
#define IC 512
#define HC 512
#define L_DIM 2
#define K1 1024      // IC + HC (weight row stride)
#define N1 1024      // 2 * HC
#define NB 128       // serial blocks (1 CTA/SM, co-resident)
#define NT 512       // serial threads per block (16 warps)

#define M_ALL (T_DIM * B_DIM)          // 32768
#define N_ALL (N1 + HC)                // 1536

#define OUT_ACT ((size_t)T_DIM * B_DIM * HC)

// ---------------- device-global scratch (allocation-free rule) ----------------
__device__ float g_act [(size_t)T_DIM * B_DIM * HC];
__device__ float g_pre1[(size_t)T_DIM * B_DIM * N1];
__device__ float g_pre2[(size_t)T_DIM * B_DIM * HC];
__device__ float g_h [B_DIM * HC];
__device__ float g_z [B_DIM * HC];
__device__ __nv_bfloat16 g_hh [B_DIM * HC];   // h  split hi
__device__ __nv_bfloat16 g_hl [B_DIM * HC];   // h  split lo
__device__ __nv_bfloat16 g_rhh[B_DIM * HC];   // rh split hi
__device__ __nv_bfloat16 g_rhl[B_DIM * HC];   // rh split lo
__device__ __nv_bfloat16 g_ahi[(size_t)M_ALL * IC];
__device__ __nv_bfloat16 g_alo[(size_t)M_ALL * IC];
__device__ __nv_bfloat16 g_whi[(size_t)N_ALL * IC];
__device__ __nv_bfloat16 g_wlo[(size_t)N_ALL * IC];
__device__ unsigned g_f1[4 * 32];      // [bg1][jg1] phase-1 done flags
__device__ unsigned g_f2[8 * 16];      // [bg2][jg2] phase-2 done flags
__device__ unsigned g_bar_cnt = 0;
__device__ unsigned g_bar_gen = 0;
__device__ unsigned g_dead    = 0;

__device__ __forceinline__ unsigned ld_u32_cg(const unsigned* p) {
    unsigned v;
    asm volatile("ld.global.cg.u32 %0, [%1];" : "=r"(v) : "l"(p) : "memory");
    return v;
}
__device__ __forceinline__ unsigned ld_acq(const unsigned* p) {
    unsigned v;
    asm volatile("ld.acquire.gpu.u32 %0, [%1];" : "=r"(v) : "l"(p) : "memory");
    return v;
}
__device__ __forceinline__ void st_rel(unsigned* p, unsigned v) {
    asm volatile("st.release.gpu.u32 [%0], %1;" :: "l"(p), "r"(v) : "memory");
}

// Full grid barrier (round-10 proven) — used ONCE per launch, after init.
__device__ __forceinline__ void grid_bar(unsigned target) {
    __syncthreads();
    if (threadIdx.x == 0) {
        if (ld_u32_cg(&g_dead) == 0u) {
            __threadfence();
            unsigned t = atomicAdd(&g_bar_cnt, 1u);
            if (t == NB - 1) {
                g_bar_cnt = 0;
                __threadfence();
                atomicExch(&g_bar_gen, target);
            } else {
                int it = 0;
                while (ld_u32_cg(&g_bar_gen) != target) {
                    if (++it > (1 << 20)) { atomicExch(&g_dead, 1u); break; }
                }
            }
            __threadfence();
        }
    }
    __syncthreads();
}

// Point-to-point wait: warp 0 polls 32 contiguous flags (one coalesced 128B
// read per iteration) with acquire semantics; bar.sync publishes to the CTA.
// Optionally sets this CTA's own flag first (after the caller's __syncthreads
// ordered all data stores). Bounded spin -> terminating wrong answer.
__device__ __forceinline__ void flag_set_and_wait(unsigned* own, unsigned* base,
                                                  unsigned ep) {
    __syncthreads();                     // all data stores of this CTA done
    if (threadIdx.x < 32) {
        if (own && threadIdx.x == 0) st_rel(own, ep);
        if (base) {
            if (ld_u32_cg(&g_dead) == 0u) {
                int it = 0;
                for (;;) {
                    unsigned v = ld_acq(&base[threadIdx.x]);
                    bool ok = (int)(v - ep) >= 0;
                    if (__all_sync(0xffffffffu, ok)) break;
                    if (++it > (1 << 20)) { st_rel(&g_dead, 1u); break; }
                }
            }
        }
    }
    __syncthreads();                     // publish acquired data CTA-wide
}

// ---------------- fp32 -> (bf16 hi, bf16 lo) split ----------------
__device__ __forceinline__ void split4(float4 v, uint2& hi, uint2& lo) {
    __nv_bfloat16 h0 = __float2bfloat16_rn(v.x);
    __nv_bfloat16 h1 = __float2bfloat16_rn(v.y);
    __nv_bfloat16 h2 = __float2bfloat16_rn(v.z);
    __nv_bfloat16 h3 = __float2bfloat16_rn(v.w);
    __nv_bfloat16 l0 = __float2bfloat16_rn(v.x - __bfloat162float(h0));
    __nv_bfloat16 l1 = __float2bfloat16_rn(v.y - __bfloat162float(h1));
    __nv_bfloat16 l2 = __float2bfloat16_rn(v.z - __bfloat162float(h2));
    __nv_bfloat16 l3 = __float2bfloat16_rn(v.w - __bfloat162float(h3));
    hi.x = (unsigned)__bfloat16_as_ushort(h0) | ((unsigned)__bfloat16_as_ushort(h1) << 16);
    hi.y = (unsigned)__bfloat16_as_ushort(h2) | ((unsigned)__bfloat16_as_ushort(h3) << 16);
    lo.x = (unsigned)__bfloat16_as_ushort(l0) | ((unsigned)__bfloat16_as_ushort(l1) << 16);
    lo.y = (unsigned)__bfloat16_as_ushort(l2) | ((unsigned)__bfloat16_as_ushort(l3) << 16);
}

__device__ __forceinline__ void split1(float v, __nv_bfloat16& hi, __nv_bfloat16& lo) {
    hi = __float2bfloat16_rn(v);
    lo = __float2bfloat16_rn(v - __bfloat162float(hi));
}

__global__ void __launch_bounds__(256)
conv_act(const float* __restrict__ x, int l)
{
    const float* lin = (l == 0) ? x : g_act;
    size_t i = (size_t)blockIdx.x * 256 + threadIdx.x;
    float4 v = ((const float4*)lin)[i];
    uint2 hi, lo;
    split4(v, hi, lo);
    ((uint2*)g_ahi)[i] = hi;
    ((uint2*)g_alo)[i] = lo;
}

__global__ void __launch_bounds__(256)
conv_w(const float* __restrict__ W1, const float* __restrict__ W2, int l)
{
    size_t i = (size_t)blockIdx.x * 256 + threadIdx.x;
    int n  = (int)(i >> 7);
    int k4 = (int)(i & 127);
    const float* src = (n < N1)
        ? (W1 + (size_t)l * N1 * K1 + (size_t)n * K1 + k4 * 4)
        : (W2 + (size_t)l * HC * K1 + (size_t)(n - N1) * K1 + k4 * 4);
    float4 v = *(const float4*)src;
    uint2 hi, lo;
    split4(v, hi, lo);
    ((uint2*)g_whi)[(size_t)n * 128 + k4] = hi;
    ((uint2*)g_wlo)[(size_t)n * 128 + k4] = lo;
}

// =====================================================================
// mma hoist (unchanged, proven): bf16 two-term split tensor GEMM.
// =====================================================================
#define MBM 128
#define MBN 64
#define MBK 32
#define SAPAD 40

__device__ __forceinline__ void mma16816(float* c, const unsigned* a, const unsigned* b) {
    asm volatile(
        "mma.sync.aligned.m16n8k16.row.col.f32.bf16.bf16.f32 "
        "{%0,%1,%2,%3}, {%4,%5,%6,%7}, {%8,%9}, {%0,%1,%2,%3};\n"
        : "+f"(c[0]), "+f"(c[1]), "+f"(c[2]), "+f"(c[3])
        : "r"(a[0]), "r"(a[1]), "r"(a[2]), "r"(a[3]), "r"(b[0]), "r"(b[1]));
}

__global__ void __launch_bounds__(256)
mma_hoist(const float* __restrict__ b1, const float* __restrict__ b2, int l)
{
    __shared__ __nv_bfloat16 sA[2][MBM][SAPAD];
    __shared__ __nv_bfloat16 sB[2][MBN][SAPAD];

    const int bn  = blockIdx.x;
    const int m0  = blockIdx.y * MBM;
    const int tid = threadIdx.x;
    const int wid = tid >> 5, lane = tid & 31;
    const int wm  = wid & 3;
    const int wn  = wid >> 2;

    float* outp;  const float* bp;  int nstr, n0, wrow0;
    if (bn < 16) { n0 = bn * MBN;        wrow0 = n0;       outp = g_pre1; nstr = N1; bp = b1 + l * N1 + n0; }
    else         { n0 = (bn - 16) * MBN; wrow0 = N1 + n0;  outp = g_pre2; nstr = HC; bp = b2 + l * HC + n0; }

    const __nv_bfloat16* segA[3] = { g_ahi, g_ahi, g_alo };
    const __nv_bfloat16* segW[3] = { g_whi, g_wlo, g_whi };

    const int ar = tid >> 2;
    const int aq = (tid & 3) * 8;

    float acc[2][4][4];
    #pragma unroll
    for (int mt = 0; mt < 2; ++mt)
        #pragma unroll
        for (int nt = 0; nt < 4; ++nt)
            #pragma unroll
            for (int q = 0; q < 4; ++q) acc[mt][nt][q] = 0.f;

    {
        const __nv_bfloat16* A = segA[0];
        const __nv_bfloat16* W = segW[0];
        uint4 a0 = *(const uint4*)(A + (size_t)(m0 + ar) * IC + aq);
        uint4 a1 = *(const uint4*)(A + (size_t)(m0 + ar + 64) * IC + aq);
        uint4 w0 = *(const uint4*)(W + (size_t)(wrow0 + ar) * IC + aq);
        *(uint4*)&sA[0][ar][aq]      = a0;
        *(uint4*)&sA[0][ar + 64][aq] = a1;
        *(uint4*)&sB[0][ar][aq]      = w0;
    }
    __syncthreads();

    const int NIT = 48;
    for (int it = 0; it < NIT; ++it) {
        const int cur = it & 1;
        const bool more = (it + 1) < NIT;
        uint4 na0, na1, nw0;
        if (more) {
            int seg = (it + 1) >> 4;
            int kt  = ((it + 1) & 15) * MBK;
            const __nv_bfloat16* A = segA[seg];
            const __nv_bfloat16* W = segW[seg];
            na0 = *(const uint4*)(A + (size_t)(m0 + ar) * IC + kt + aq);
            na1 = *(const uint4*)(A + (size_t)(m0 + ar + 64) * IC + kt + aq);
            nw0 = *(const uint4*)(W + (size_t)(wrow0 + ar) * IC + kt + aq);
        }

        #pragma unroll
        for (int ks = 0; ks < MBK; ks += 16) {
            const int kb = ks + (lane & 3) * 2;
            unsigned af[2][4], bf[4][2];
            #pragma unroll
            for (int mt = 0; mt < 2; ++mt) {
                int r = wm * 32 + mt * 16 + (lane >> 2);
                af[mt][0] = *(const unsigned*)&sA[cur][r][kb];
                af[mt][1] = *(const unsigned*)&sA[cur][r + 8][kb];
                af[mt][2] = *(const unsigned*)&sA[cur][r][kb + 8];
                af[mt][3] = *(const unsigned*)&sA[cur][r + 8][kb + 8];
            }
            #pragma unroll
            for (int nt = 0; nt < 4; ++nt) {
                int c = wn * 32 + nt * 8 + (lane >> 2);
                bf[nt][0] = *(const unsigned*)&sB[cur][c][kb];
                bf[nt][1] = *(const unsigned*)&sB[cur][c][kb + 8];
            }
            #pragma unroll
            for (int mt = 0; mt < 2; ++mt)
                #pragma unroll
                for (int nt = 0; nt < 4; ++nt)
                    mma16816(acc[mt][nt], af[mt], bf[nt]);
        }

        if (more) {
            const int nxt = cur ^ 1;
            *(uint4*)&sA[nxt][ar][aq]      = na0;
            *(uint4*)&sA[nxt][ar + 64][aq] = na1;
            *(uint4*)&sB[nxt][ar][aq]      = nw0;
            __syncthreads();
        }
    }

    #pragma unroll
    for (int mt = 0; mt < 2; ++mt) {
        #pragma unroll
        for (int nt = 0; nt < 4; ++nt) {
            int r  = m0 + wm * 32 + mt * 16 + (lane >> 2);
            int cl = wn * 32 + nt * 8 + (lane & 3) * 2;
            float bx = bp[cl], by = bp[cl + 1];
            float2 o0 = { acc[mt][nt][0] + bx, acc[mt][nt][1] + by };
            float2 o1 = { acc[mt][nt][2] + bx, acc[mt][nt][3] + by };
            *(float2*)(outp + (size_t)r * nstr + n0 + cl)       = o0;
            *(float2*)(outp + (size_t)(r + 8) * nstr + n0 + cl) = o1;
        }
    }
}

// =====================================================================
// Serial kernel: round-12 compute verbatim; per-step global barriers
// replaced by point-to-point flags between true dependents only.
//  f2[bg2][jg2]: h(t) ready.   Phase-1 waits 32 flags (bg2 in {2bg1,2bg1+1}).
//  f1[bg1][jg1]: rh/z(t) ready. Phase-2 waits 32 flags (bg1 = bg2>>1).
//  Each wait also clears the corresponding WAR (the flagged CTAs are
//  exactly the readers of the rows about to be overwritten).
// =====================================================================
#define WS 520      // smem row stride in halfs
#define OFF_W1H 0
#define OFF_W1L 33280
#define OFF_W2H 66560
#define OFF_W2L 99840
#define OFF_HH  133120
#define OFF_HL  149760
#define OFF_RED 166400
#define SER_SMEM_BYTES 182784

__device__ __forceinline__ uint32_t s2u(const void* p) {
    return (uint32_t)__cvta_generic_to_shared(p);
}
__device__ __forceinline__ void ldsm_x4(unsigned* r, uint32_t addr) {
    asm volatile("ldmatrix.sync.aligned.m8n8.x4.shared.b16 {%0,%1,%2,%3}, [%4];"
                 : "=r"(r[0]), "=r"(r[1]), "=r"(r[2]), "=r"(r[3]) : "r"(addr));
}

__global__ void __launch_bounds__(NT, 1)
serial_kernel(const float* __restrict__ hiddens,
              const float* __restrict__ W1, const float* __restrict__ W2,
              float* __restrict__ out, int l)
{
    extern __shared__ char smc[];
    __nv_bfloat16* sW1h = (__nv_bfloat16*)(smc + OFF_W1H);
    __nv_bfloat16* sW1l = (__nv_bfloat16*)(smc + OFF_W1L);
    __nv_bfloat16* sW2h = (__nv_bfloat16*)(smc + OFF_W2H);
    __nv_bfloat16* sW2l = (__nv_bfloat16*)(smc + OFF_W2L);
    __nv_bfloat16* sHh  = (__nv_bfloat16*)(smc + OFF_HH);
    __nv_bfloat16* sHl  = (__nv_bfloat16*)(smc + OFF_HL);
    float*         red  = (float*)(smc + OFF_RED);   // [ks 8][jt 4][lane 32][4]

    const int tid  = threadIdx.x;
    const int bid  = blockIdx.x;
    const int wp   = tid >> 5;
    const int lane = tid & 31;

    const int jg1 = bid >> 2;   // 0..31
    const int bg1 = bid & 3;    // 0..3
    const int jg2 = bid >> 3;   // 0..15
    const int bg2 = bid & 7;    // 0..7

    float* lout = (l == 0) ? g_act : out;

    const int jl1 = tid & 31, bl1 = tid >> 5;           // phase1: 32j x 16b
    const int j1  = jg1 * 32 + jl1;
    const int b1o = bg1 * 16 + bl1;
    const int jl2 = tid & 31, bl2 = (tid >> 5) & 7;     // phase2: 32j x 8b
    const int j2  = jg2 * 32 + jl2;
    const int b2o = bg2 * 8 + bl2;
    const bool p2own = (tid < 256);

    const int lf1 = (bl1 & 7) * 4 + ((jl1 & 7) >> 1);
    const int cc1 = (jl1 & 1) + ((bl1 >> 3) << 1);
    const int jt1 = jl1 >> 3;
    const int lf2 = bl2 * 4 + ((jl2 & 7) >> 1);
    const int cc2 = jl2 & 1;
    const int jt2 = jl2 >> 3;

    // ---- stage bf16-split weights once per layer ----
    for (int idx = tid; idx < 32 * 128; idx += NT) {    // idx over float4
        int jl = idx >> 7, k4 = idx & 127;
        float4 v1 = *(const float4*)&W1[((size_t)l * N1 + jg1 * 32 + jl) * K1 + IC + k4 * 4];
        float4 v2 = *(const float4*)&W2[((size_t)l * HC + jg2 * 32 + jl) * K1 + IC + k4 * 4];
        uint2 hi, lo;
        split4(v1, hi, lo);
        *(uint2*)&sW1h[jl * WS + k4 * 4] = hi;
        *(uint2*)&sW1l[jl * WS + k4 * 4] = lo;
        split4(v2, hi, lo);
        *(uint2*)&sW2h[jl * WS + k4 * 4] = hi;
        *(uint2*)&sW2l[jl * WS + k4 * 4] = lo;
    }

    // Init hidden state (fp32 + split) and reset this CTA's flags
    { int i = bid * NT + tid;
      if (i < B_DIM * HC) {
          float v = hiddens[l * HC + (i & (HC - 1))];
          g_h[i] = v;
          __nv_bfloat16 hi, lo;
          split1(v, hi, lo);
          g_hh[i] = hi;  g_hl[i] = lo;
      } }
    if (tid == 0) {
        g_f1[bg1 * 32 + jg1] = 0;
        g_f2[bg2 * 16 + jg2] = 0;
    }

    unsigned ep = ld_u32_cg(&g_bar_gen);
    grid_bar(++ep);      // one full barrier: init + flag resets visible

    unsigned* f1_own   = &g_f1[bg1 * 32 + jg1];
    unsigned* f2_own   = &g_f2[bg2 * 16 + jg2];
    unsigned* f1_watch = &g_f1[(bg2 >> 1) * 32];        // 32 flags
    unsigned* f2_watch = &g_f2[(bg1 * 2) * 16];         // 32 flags

    // LDSM lane addressing (same fragment layout as verified scalar loads)
    const int lrow = (lane & 7) + ((lane >> 3) & 1) * 8;   // 0..15
    const int lkof = (lane >> 4) << 3;                     // 0 or 8

    for (int t = 0; t < T_DIM; ++t) {
        const unsigned sep = (unsigned)(t + 1);

        // ---- wait h(t-1) ready from my 32 phase-2 producers (t>0) ----
        if (t > 0) flag_set_and_wait(nullptr, f2_watch, sep - 1);

        float pre1v = __ldcg(&g_pre1[((size_t)t * B_DIM + b1o) * N1 + j1]);
        float hv = 0.f;
        if (jg1 < 16) hv = __ldcg(&g_h[b1o * HC + j1]);
        float pre2v = 0.f, hov = 0.f;
        if (p2own) {
            pre2v = __ldcg(&g_pre2[((size_t)t * B_DIM + b2o) * HC + j2]);
            hov   = __ldcg(&g_h[b2o * HC + j2]);   // self-written at t-1
        }

        // ---- stage h[bg1*16..+16][:] pre-split: raw uint4 copies ----
        #pragma unroll
        for (int q = 0; q < 2; ++q) {
            int i8 = q * NT + tid;             // over uint4 (8 halfs); 1024 total
            int row = i8 >> 6, c8 = i8 & 63;
            uint4 vh = __ldcg((const uint4*)&g_hh[(size_t)(bg1 * 16 + row) * HC + c8 * 8]);
            uint4 vl = __ldcg((const uint4*)&g_hl[(size_t)(bg1 * 16 + row) * HC + c8 * 8]);
            *(uint4*)&sHh[row * WS + c8 * 8] = vh;
            *(uint4*)&sHl[row * WS + c8 * 8] = vl;
        }
        __syncthreads();

        // ---- Phase 1 compute: h @ W1h^T via LDSM + mma ----
        {
            const int ks = wp >> 1;
            const int jp = wp & 1;
            float acc[2][4];
            #pragma unroll
            for (int jj = 0; jj < 2; ++jj)
                #pragma unroll
                for (int q = 0; q < 4; ++q) acc[jj][q] = 0.f;
            #pragma unroll
            for (int cc = 0; cc < 4; ++cc) {
                int kb0 = ks * 64 + cc * 16 + lkof;
                unsigned ah[4], al[4], wh[4], wl[4];
                ldsm_x4(ah, s2u(&sHh[lrow * WS + kb0]));
                ldsm_x4(al, s2u(&sHl[lrow * WS + kb0]));
                ldsm_x4(wh, s2u(&sW1h[(jp * 16 + lrow) * WS + kb0]));
                ldsm_x4(wl, s2u(&sW1l[(jp * 16 + lrow) * WS + kb0]));
                #pragma unroll
                for (int jj = 0; jj < 2; ++jj) {
                    unsigned bh[2] = { wh[jj], wh[jj + 2] };
                    unsigned bl_[2] = { wl[jj], wl[jj + 2] };
                    mma16816(acc[jj], ah, bh);
                    mma16816(acc[jj], ah, bl_);
                    mma16816(acc[jj], al, bh);
                }
            }
            #pragma unroll
            for (int jj = 0; jj < 2; ++jj)
                *(float4*)&red[((ks * 4 + jp * 2 + jj) * 32 + lane) * 4] =
                    *(float4*)acc[jj];
        }
        __syncthreads();

        // ---- Phase 1 epilogue: r,z; rh written pre-split ----
        {
            float s = 0.f;
            #pragma unroll
            for (int ks = 0; ks < 8; ++ks)
                s += red[((ks * 4 + jt1) * 32 + lf1) * 4 + cc1];
            float pre = s + pre1v;
            float sg  = __fdividef(1.f, 1.f + __expf(-pre));
            if (jg1 < 16) {
                float rhv = sg * hv;
                __nv_bfloat16 hi, lo;
                split1(rhv, hi, lo);
                g_rhh[b1o * HC + j1] = hi;
                g_rhl[b1o * HC + j1] = lo;
            } else {
                g_z[b1o * HC + (j1 - HC)] = sg;
            }
        }

        // ---- publish rh/z; wait my 32 phase-1 producers ----
        flag_set_and_wait(f1_own, f1_watch, sep);

        // ---- stage rh[bg2*8..+8][:] pre-split; prefetch z ----
        float zv = 0.f;
        if (p2own) zv = __ldcg(&g_z[b2o * HC + j2]);
        {
            int i8 = tid;                       // 512 uint4 cover 8 rows
            int row = i8 >> 6, c8 = i8 & 63;
            uint4 vh = __ldcg((const uint4*)&g_rhh[(size_t)(bg2 * 8 + row) * HC + c8 * 8]);
            uint4 vl = __ldcg((const uint4*)&g_rhl[(size_t)(bg2 * 8 + row) * HC + c8 * 8]);
            *(uint4*)&sHh[row * WS + c8 * 8] = vh;
            *(uint4*)&sHl[row * WS + c8 * 8] = vl;
        }
        __syncthreads();

        // ---- Phase 2 compute (rows 8..15 stale/unused, matches R12) ----
        {
            const int ks = wp >> 1;
            const int jp = wp & 1;
            float acc[2][4];
            #pragma unroll
            for (int jj = 0; jj < 2; ++jj)
                #pragma unroll
                for (int q = 0; q < 4; ++q) acc[jj][q] = 0.f;
            #pragma unroll
            for (int cc = 0; cc < 4; ++cc) {
                int kb0 = ks * 64 + cc * 16 + lkof;
                unsigned ah[4], al[4], wh[4], wl[4];
                ldsm_x4(ah, s2u(&sHh[lrow * WS + kb0]));
                ldsm_x4(al, s2u(&sHl[lrow * WS + kb0]));
                ldsm_x4(wh, s2u(&sW2h[(jp * 16 + lrow) * WS + kb0]));
                ldsm_x4(wl, s2u(&sW2l[(jp * 16 + lrow) * WS + kb0]));
                #pragma unroll
                for (int jj = 0; jj < 2; ++jj) {
                    unsigned bh[2] = { wh[jj], wh[jj + 2] };
                    unsigned bl_[2] = { wl[jj], wl[jj + 2] };
                    mma16816(acc[jj], ah, bh);
                    mma16816(acc[jj], ah, bl_);
                    mma16816(acc[jj], al, bh);
                }
            }
            #pragma unroll
            for (int jj = 0; jj < 2; ++jj)
                *(float4*)&red[((ks * 4 + jp * 2 + jj) * 32 + lane) * 4] =
                    *(float4*)acc[jj];
        }
        __syncthreads();

        // ---- Phase 2 epilogue: h update, written fp32 + pre-split ----
        if (p2own) {
            float s = 0.f;
            #pragma unroll
            for (int ks = 0; ks < 8; ++ks)
                s += red[((ks * 4 + jt2) * 32 + lf2) * 4 + cc2];
            float x2v = s + pre2v;
            float gg  = 1.f - __fdividef(2.f, __expf(2.f * x2v) + 1.f);
            float hn  = zv * hov + (1.f - zv) * gg;
            g_h[b2o * HC + j2] = hn;
            __nv_bfloat16 hi, lo;
            split1(hn, hi, lo);
            g_hh[b2o * HC + j2] = hi;
            g_hl[b2o * HC + j2] = lo;
            lout[((size_t)t * B_DIM + b2o) * HC + j2] = hn;
            if (t == T_DIM - 1)
                out[OUT_ACT + (size_t)l * B_DIM * HC + b2o * HC + j2] = hn;
        }

        // ---- publish h(t); next iteration's f2-wait consumes it ----
        flag_set_and_wait(f2_own, nullptr, sep);
    }
}

extern "C" void kernel_launch(void* const* d_in, const int* in_sizes, int n_in,
                              void* d_out, int out_size) {
    const float* x       = (const float*)d_in[0];
    const float* hiddens = (const float*)d_in[1];
    const float* W1      = (const float*)d_in[2];
    const float* b1      = (const float*)d_in[3];
    const float* W2      = (const float*)d_in[4];
    const float* b2      = (const float*)d_in[5];
    float* out = (float*)d_out;

    cudaFuncSetAttribute(serial_kernel,
                         cudaFuncAttributeMaxDynamicSharedMemorySize,
                         SER_SMEM_BYTES);

    for (int l = 0; l < L_DIM; ++l) {
        conv_act<<<M_ALL * IC / 4 / 256, 256>>>(x, l);
        conv_w  <<<N_ALL * IC / 4 / 256, 256>>>(W1, W2, l);
        mma_hoist<<<dim3(24, M_ALL / MBM), 256>>>(b1, b2, l);
        serial_kernel<<<NB, NT, SER_SMEM_BYTES>>>(hiddens, W1, W2, out, l);
    }
}

// round 14
// speedup vs baseline: 1.4678x; 1.2350x over previous
#include <cuda_runtime.h>
#include <cuda_bf16.h>
#include <math.h>
#include <stdint.h>

#define T_DIM 512
#define B_DIM 64
#define IC 512
#define HC 512
#define L_DIM 2
#define K1 1024      // IC + HC (weight row stride)
#define N1 1024      // 2 * HC
#define NB 128       // serial blocks (1 CTA/SM, co-resident)
#define NT 512       // serial threads per block (16 warps)

#define M_ALL (T_DIM * B_DIM)          // 32768
#define N_ALL (N1 + HC)                // 1536

#define OUT_ACT ((size_t)T_DIM * B_DIM * HC)

// ---------------- device-global scratch (allocation-free rule) ----------------
__device__ float g_act [(size_t)T_DIM * B_DIM * HC];
__device__ float g_pre1[(size_t)T_DIM * B_DIM * N1];
__device__ float g_pre2[(size_t)T_DIM * B_DIM * HC];
__device__ float g_h [B_DIM * HC];
__device__ float g_z [B_DIM * HC];
__device__ __nv_bfloat16 g_hh [B_DIM * HC];   // h  split hi
__device__ __nv_bfloat16 g_hl [B_DIM * HC];   // h  split lo
__device__ __nv_bfloat16 g_rhh[B_DIM * HC];   // rh split hi
__device__ __nv_bfloat16 g_rhl[B_DIM * HC];   // rh split lo
__device__ __nv_bfloat16 g_ahi[(size_t)M_ALL * IC];
__device__ __nv_bfloat16 g_alo[(size_t)M_ALL * IC];
__device__ __nv_bfloat16 g_whi[(size_t)N_ALL * IC];
__device__ __nv_bfloat16 g_wlo[(size_t)N_ALL * IC];
// flags: per half (A=0,B=1)
__device__ unsigned g_f1[2 * 64];      // [half][bg1 2][jg1 32] phase-1 done
__device__ unsigned g_f2[2 * 64];      // [half][bg2 4][jg2 16] phase-2 done
__device__ unsigned g_bar_cnt = 0;
__device__ unsigned g_bar_gen = 0;
__device__ unsigned g_dead    = 0;

__device__ __forceinline__ unsigned ld_u32_cg(const unsigned* p) {
    unsigned v;
    asm volatile("ld.global.cg.u32 %0, [%1];" : "=r"(v) : "l"(p) : "memory");
    return v;
}
__device__ __forceinline__ unsigned ld_acq(const unsigned* p) {
    unsigned v;
    asm volatile("ld.acquire.gpu.u32 %0, [%1];" : "=r"(v) : "l"(p) : "memory");
    return v;
}
__device__ __forceinline__ void st_rel(unsigned* p, unsigned v) {
    asm volatile("st.release.gpu.u32 [%0], %1;" :: "l"(p), "r"(v) : "memory");
}

// Full grid barrier (round-10 proven) — used ONCE per launch, after init.
__device__ __forceinline__ void grid_bar(unsigned target) {
    __syncthreads();
    if (threadIdx.x == 0) {
        if (ld_u32_cg(&g_dead) == 0u) {
            __threadfence();
            unsigned t = atomicAdd(&g_bar_cnt, 1u);
            if (t == NB - 1) {
                g_bar_cnt = 0;
                __threadfence();
                atomicExch(&g_bar_gen, target);
            } else {
                int it = 0;
                while (ld_u32_cg(&g_bar_gen) != target) {
                    if (++it > (1 << 20)) { atomicExch(&g_dead, 1u); break; }
                }
            }
            __threadfence();
        }
    }
    __syncthreads();
}

// Point-to-point: warp 0 optionally sets own flag (after caller-side
// __syncthreads ordered the data stores) then polls 32 contiguous flags with
// acquire; bar.sync publishes CTA-wide. Bounded spin -> terminating.
__device__ __forceinline__ void flag_set_and_wait(unsigned* own, unsigned* base,
                                                  unsigned ep) {
    __syncthreads();
    if (threadIdx.x < 32) {
        if (own && threadIdx.x == 0) st_rel(own, ep);
        if (base) {
            if (ld_u32_cg(&g_dead) == 0u) {
                int it = 0;
                for (;;) {
                    unsigned v = ld_acq(&base[threadIdx.x]);
                    bool ok = (int)(v - ep) >= 0;
                    if (__all_sync(0xffffffffu, ok)) break;
                    if (++it > (1 << 20)) { st_rel(&g_dead, 1u); break; }
                }
            }
        }
    }
    __syncthreads();
}

// ---------------- fp32 -> (bf16 hi, bf16 lo) split ----------------
__device__ __forceinline__ void split4(float4 v, uint2& hi, uint2& lo) {
    __nv_bfloat16 h0 = __float2bfloat16_rn(v.x);
    __nv_bfloat16 h1 = __float2bfloat16_rn(v.y);
    __nv_bfloat16 h2 = __float2bfloat16_rn(v.z);
    __nv_bfloat16 h3 = __float2bfloat16_rn(v.w);
    __nv_bfloat16 l0 = __float2bfloat16_rn(v.x - __bfloat162float(h0));
    __nv_bfloat16 l1 = __float2bfloat16_rn(v.y - __bfloat162float(h1));
    __nv_bfloat16 l2 = __float2bfloat16_rn(v.z - __bfloat162float(h2));
    __nv_bfloat16 l3 = __float2bfloat16_rn(v.w - __bfloat162float(h3));
    hi.x = (unsigned)__bfloat16_as_ushort(h0) | ((unsigned)__bfloat16_as_ushort(h1) << 16);
    hi.y = (unsigned)__bfloat16_as_ushort(h2) | ((unsigned)__bfloat16_as_ushort(h3) << 16);
    lo.x = (unsigned)__bfloat16_as_ushort(l0) | ((unsigned)__bfloat16_as_ushort(l1) << 16);
    lo.y = (unsigned)__bfloat16_as_ushort(l2) | ((unsigned)__bfloat16_as_ushort(l3) << 16);
}

__device__ __forceinline__ void split1(float v, __nv_bfloat16& hi, __nv_bfloat16& lo) {
    hi = __float2bfloat16_rn(v);
    lo = __float2bfloat16_rn(v - __bfloat162float(hi));
}

__global__ void __launch_bounds__(256)
conv_act(const float* __restrict__ x, int l)
{
    const float* lin = (l == 0) ? x : g_act;
    size_t i = (size_t)blockIdx.x * 256 + threadIdx.x;
    float4 v = ((const float4*)lin)[i];
    uint2 hi, lo;
    split4(v, hi, lo);
    ((uint2*)g_ahi)[i] = hi;
    ((uint2*)g_alo)[i] = lo;
}

__global__ void __launch_bounds__(256)
conv_w(const float* __restrict__ W1, const float* __restrict__ W2, int l)
{
    size_t i = (size_t)blockIdx.x * 256 + threadIdx.x;
    int n  = (int)(i >> 7);
    int k4 = (int)(i & 127);
    const float* src = (n < N1)
        ? (W1 + (size_t)l * N1 * K1 + (size_t)n * K1 + k4 * 4)
        : (W2 + (size_t)l * HC * K1 + (size_t)(n - N1) * K1 + k4 * 4);
    float4 v = *(const float4*)src;
    uint2 hi, lo;
    split4(v, hi, lo);
    ((uint2*)g_whi)[(size_t)n * 128 + k4] = hi;
    ((uint2*)g_wlo)[(size_t)n * 128 + k4] = lo;
}

// =====================================================================
// mma hoist (unchanged, proven): bf16 two-term split tensor GEMM.
// =====================================================================
#define MBM 128
#define MBN 64
#define MBK 32
#define SAPAD 40

__device__ __forceinline__ void mma16816(float* c, const unsigned* a, const unsigned* b) {
    asm volatile(
        "mma.sync.aligned.m16n8k16.row.col.f32.bf16.bf16.f32 "
        "{%0,%1,%2,%3}, {%4,%5,%6,%7}, {%8,%9}, {%0,%1,%2,%3};\n"
        : "+f"(c[0]), "+f"(c[1]), "+f"(c[2]), "+f"(c[3])
        : "r"(a[0]), "r"(a[1]), "r"(a[2]), "r"(a[3]), "r"(b[0]), "r"(b[1]));
}

__global__ void __launch_bounds__(256)
mma_hoist(const float* __restrict__ b1, const float* __restrict__ b2, int l)
{
    __shared__ __nv_bfloat16 sA[2][MBM][SAPAD];
    __shared__ __nv_bfloat16 sB[2][MBN][SAPAD];

    const int bn  = blockIdx.x;
    const int m0  = blockIdx.y * MBM;
    const int tid = threadIdx.x;
    const int wid = tid >> 5, lane = tid & 31;
    const int wm  = wid & 3;
    const int wn  = wid >> 2;

    float* outp;  const float* bp;  int nstr, n0, wrow0;
    if (bn < 16) { n0 = bn * MBN;        wrow0 = n0;       outp = g_pre1; nstr = N1; bp = b1 + l * N1 + n0; }
    else         { n0 = (bn - 16) * MBN; wrow0 = N1 + n0;  outp = g_pre2; nstr = HC; bp = b2 + l * HC + n0; }

    const __nv_bfloat16* segA[3] = { g_ahi, g_ahi, g_alo };
    const __nv_bfloat16* segW[3] = { g_whi, g_wlo, g_whi };

    const int ar = tid >> 2;
    const int aq = (tid & 3) * 8;

    float acc[2][4][4];
    #pragma unroll
    for (int mt = 0; mt < 2; ++mt)
        #pragma unroll
        for (int nt = 0; nt < 4; ++nt)
            #pragma unroll
            for (int q = 0; q < 4; ++q) acc[mt][nt][q] = 0.f;

    {
        const __nv_bfloat16* A = segA[0];
        const __nv_bfloat16* W = segW[0];
        uint4 a0 = *(const uint4*)(A + (size_t)(m0 + ar) * IC + aq);
        uint4 a1 = *(const uint4*)(A + (size_t)(m0 + ar + 64) * IC + aq);
        uint4 w0 = *(const uint4*)(W + (size_t)(wrow0 + ar) * IC + aq);
        *(uint4*)&sA[0][ar][aq]      = a0;
        *(uint4*)&sA[0][ar + 64][aq] = a1;
        *(uint4*)&sB[0][ar][aq]      = w0;
    }
    __syncthreads();

    const int NIT = 48;
    for (int it = 0; it < NIT; ++it) {
        const int cur = it & 1;
        const bool more = (it + 1) < NIT;
        uint4 na0, na1, nw0;
        if (more) {
            int seg = (it + 1) >> 4;
            int kt  = ((it + 1) & 15) * MBK;
            const __nv_bfloat16* A = segA[seg];
            const __nv_bfloat16* W = segW[seg];
            na0 = *(const uint4*)(A + (size_t)(m0 + ar) * IC + kt + aq);
            na1 = *(const uint4*)(A + (size_t)(m0 + ar + 64) * IC + kt + aq);
            nw0 = *(const uint4*)(W + (size_t)(wrow0 + ar) * IC + kt + aq);
        }

        #pragma unroll
        for (int ks = 0; ks < MBK; ks += 16) {
            const int kb = ks + (lane & 3) * 2;
            unsigned af[2][4], bf[4][2];
            #pragma unroll
            for (int mt = 0; mt < 2; ++mt) {
                int r = wm * 32 + mt * 16 + (lane >> 2);
                af[mt][0] = *(const unsigned*)&sA[cur][r][kb];
                af[mt][1] = *(const unsigned*)&sA[cur][r + 8][kb];
                af[mt][2] = *(const unsigned*)&sA[cur][r][kb + 8];
                af[mt][3] = *(const unsigned*)&sA[cur][r + 8][kb + 8];
            }
            #pragma unroll
            for (int nt = 0; nt < 4; ++nt) {
                int c = wn * 32 + nt * 8 + (lane >> 2);
                bf[nt][0] = *(const unsigned*)&sB[cur][c][kb];
                bf[nt][1] = *(const unsigned*)&sB[cur][c][kb + 8];
            }
            #pragma unroll
            for (int mt = 0; mt < 2; ++mt)
                #pragma unroll
                for (int nt = 0; nt < 4; ++nt)
                    mma16816(acc[mt][nt], af[mt], bf[nt]);
        }

        if (more) {
            const int nxt = cur ^ 1;
            *(uint4*)&sA[nxt][ar][aq]      = na0;
            *(uint4*)&sA[nxt][ar + 64][aq] = na1;
            *(uint4*)&sB[nxt][ar][aq]      = nw0;
            __syncthreads();
        }
    }

    #pragma unroll
    for (int mt = 0; mt < 2; ++mt) {
        #pragma unroll
        for (int nt = 0; nt < 4; ++nt) {
            int r  = m0 + wm * 32 + mt * 16 + (lane >> 2);
            int cl = wn * 32 + nt * 8 + (lane & 3) * 2;
            float bx = bp[cl], by = bp[cl + 1];
            float2 o0 = { acc[mt][nt][0] + bx, acc[mt][nt][1] + by };
            float2 o1 = { acc[mt][nt][2] + bx, acc[mt][nt][3] + by };
            *(float2*)(outp + (size_t)r * nstr + n0 + cl)       = o0;
            *(float2*)(outp + (size_t)(r + 8) * nstr + n0 + cl) = o1;
        }
    }
}

// =====================================================================
// Serial kernel: round-13 compute verbatim; mirrored two-group batch
// pipelining. Half A = batches 0..31, half B = 32..63.
//   CTAs  0..63 : phase-1 of half A, phase-2 of half B.
//   CTAs 64..127: phase-1 of half B, phase-2 of half A.
// Per-half tiles keep round-13 shapes exactly:
//   P1: 32j x 16b  (jg1 = r>>1 in 0..31, bg1 = r&1 in 0..1)
//   P2: 32j x  8b  (jg2 = r>>2 in 0..15, bg2 = r&3 in 0..3)
// Flags per half: f1[half][bg1*32+jg1], f2[half][bg2*16+jg2].
// Each group's waits overlap the other group's mirrored compute.
// =====================================================================
#define WS 520      // smem row stride in halfs
#define OFF_W1H 0
#define OFF_W1L 33280
#define OFF_W2H 66560
#define OFF_W2L 99840
#define OFF_HH  133120
#define OFF_HL  149760
#define OFF_RED 166400
#define SER_SMEM_BYTES 182784

__device__ __forceinline__ uint32_t s2u(const void* p) {
    return (uint32_t)__cvta_generic_to_shared(p);
}
__device__ __forceinline__ void ldsm_x4(unsigned* r, uint32_t addr) {
    asm volatile("ldmatrix.sync.aligned.m8n8.x4.shared.b16 {%0,%1,%2,%3}, [%4];"
                 : "=r"(r[0]), "=r"(r[1]), "=r"(r[2]), "=r"(r[3]) : "r"(addr));
}

__global__ void __launch_bounds__(NT, 1)
serial_kernel(const float* __restrict__ hiddens,
              const float* __restrict__ W1, const float* __restrict__ W2,
              float* __restrict__ out, int l)
{
    extern __shared__ char smc[];
    __nv_bfloat16* sW1h = (__nv_bfloat16*)(smc + OFF_W1H);
    __nv_bfloat16* sW1l = (__nv_bfloat16*)(smc + OFF_W1L);
    __nv_bfloat16* sW2h = (__nv_bfloat16*)(smc + OFF_W2H);
    __nv_bfloat16* sW2l = (__nv_bfloat16*)(smc + OFF_W2L);
    __nv_bfloat16* sHh  = (__nv_bfloat16*)(smc + OFF_HH);
    __nv_bfloat16* sHl  = (__nv_bfloat16*)(smc + OFF_HL);
    float*         red  = (float*)(smc + OFF_RED);   // [ks 8][jt 4][lane 32][4]

    const int tid  = threadIdx.x;
    const int bid  = blockIdx.x;
    const int wp   = tid >> 5;
    const int lane = tid & 31;

    // ---- mirrored role assignment ----
    const int p1half = (bid < 64) ? 0 : 1;
    const int p1base = p1half * 32;            // batch base of my P1 half
    const int p2half = 1 - p1half;
    const int p2base = p2half * 32;            // batch base of my P2 half
    const int r   = bid & 63;
    const int jg1 = r >> 1;    // 0..31
    const int bg1 = r & 1;     // 0..1
    const int jg2 = r >> 2;    // 0..15
    const int bg2 = r & 3;     // 0..3

    float* lout = (l == 0) ? g_act : out;

    const int jl1 = tid & 31, bl1 = tid >> 5;           // phase1: 32j x 16b
    const int j1  = jg1 * 32 + jl1;
    const int b1o = p1base + bg1 * 16 + bl1;
    const int jl2 = tid & 31, bl2 = (tid >> 5) & 7;     // phase2: 32j x 8b
    const int j2  = jg2 * 32 + jl2;
    const int b2o = p2base + bg2 * 8 + bl2;
    const bool p2own = (tid < 256);

    const int lf1 = (bl1 & 7) * 4 + ((jl1 & 7) >> 1);
    const int cc1 = (jl1 & 1) + ((bl1 >> 3) << 1);
    const int jt1 = jl1 >> 3;
    const int lf2 = bl2 * 4 + ((jl2 & 7) >> 1);
    const int cc2 = jl2 & 1;
    const int jt2 = jl2 >> 3;

    // ---- stage bf16-split weights once per layer (same j-slices as R13) ----
    for (int idx = tid; idx < 32 * 128; idx += NT) {    // idx over float4
        int jl = idx >> 7, k4 = idx & 127;
        float4 v1 = *(const float4*)&W1[((size_t)l * N1 + jg1 * 32 + jl) * K1 + IC + k4 * 4];
        float4 v2 = *(const float4*)&W2[((size_t)l * HC + jg2 * 32 + jl) * K1 + IC + k4 * 4];
        uint2 hi, lo;
        split4(v1, hi, lo);
        *(uint2*)&sW1h[jl * WS + k4 * 4] = hi;
        *(uint2*)&sW1l[jl * WS + k4 * 4] = lo;
        split4(v2, hi, lo);
        *(uint2*)&sW2h[jl * WS + k4 * 4] = hi;
        *(uint2*)&sW2l[jl * WS + k4 * 4] = lo;
    }

    // Init hidden state (fp32 + split) and reset this CTA's flags
    { int i = bid * NT + tid;
      if (i < B_DIM * HC) {
          float v = hiddens[l * HC + (i & (HC - 1))];
          g_h[i] = v;
          __nv_bfloat16 hi, lo;
          split1(v, hi, lo);
          g_hh[i] = hi;  g_hl[i] = lo;
      } }
    if (tid == 0) {
        g_f1[p1half * 64 + bg1 * 32 + jg1] = 0;
        g_f2[p2half * 64 + bg2 * 16 + jg2] = 0;
    }

    unsigned ep = ld_u32_cg(&g_bar_gen);
    grid_bar(++ep);      // one full barrier: init + flag resets visible

    unsigned* f1_own   = &g_f1[p1half * 64 + bg1 * 32 + jg1];
    unsigned* f2_own   = &g_f2[p2half * 64 + bg2 * 16 + jg2];
    // P2 consumes rh/z of half p2half, rows bg2*8..+8 -> producers bg1=bg2>>1
    unsigned* f1_watch = &g_f1[p2half * 64 + (bg2 >> 1) * 32];      // 32 flags
    // P1 consumes h of half p1half, rows bg1*16..+16 -> producers bg2 in {2bg1,2bg1+1}
    unsigned* f2_watch = &g_f2[p1half * 64 + (bg1 * 2) * 16];       // 32 flags

    // LDSM lane addressing (unchanged)
    const int lrow = (lane & 7) + ((lane >> 3) & 1) * 8;   // 0..15
    const int lkof = (lane >> 4) << 3;                     // 0 or 8

    for (int t = 0; t < T_DIM; ++t) {
        const unsigned sep = (unsigned)(t + 1);

        // ---- wait h(t-1) of MY P1 half from its 32 phase-2 producers ----
        if (t > 0) flag_set_and_wait(nullptr, f2_watch, sep - 1);

        float pre1v = __ldcg(&g_pre1[((size_t)t * B_DIM + b1o) * N1 + j1]);
        float hv = 0.f;
        if (jg1 < 16) hv = __ldcg(&g_h[b1o * HC + j1]);
        float pre2v = 0.f, hov = 0.f;
        if (p2own) {
            pre2v = __ldcg(&g_pre2[((size_t)t * B_DIM + b2o) * HC + j2]);
            hov   = __ldcg(&g_h[b2o * HC + j2]);   // self-written at t-1
        }

        // ---- stage h[p1base + bg1*16 .. +16][:] pre-split ----
        #pragma unroll
        for (int q = 0; q < 2; ++q) {
            int i8 = q * NT + tid;             // over uint4 (8 halfs); 1024 total
            int row = i8 >> 6, c8 = i8 & 63;
            uint4 vh = __ldcg((const uint4*)&g_hh[(size_t)(p1base + bg1 * 16 + row) * HC + c8 * 8]);
            uint4 vl = __ldcg((const uint4*)&g_hl[(size_t)(p1base + bg1 * 16 + row) * HC + c8 * 8]);
            *(uint4*)&sHh[row * WS + c8 * 8] = vh;
            *(uint4*)&sHl[row * WS + c8 * 8] = vl;
        }
        __syncthreads();

        // ---- Phase 1 compute: h @ W1h^T via LDSM + mma (verbatim) ----
        {
            const int ks = wp >> 1;
            const int jp = wp & 1;
            float acc[2][4];
            #pragma unroll
            for (int jj = 0; jj < 2; ++jj)
                #pragma unroll
                for (int q = 0; q < 4; ++q) acc[jj][q] = 0.f;
            #pragma unroll
            for (int cc = 0; cc < 4; ++cc) {
                int kb0 = ks * 64 + cc * 16 + lkof;
                unsigned ah[4], al[4], wh[4], wl[4];
                ldsm_x4(ah, s2u(&sHh[lrow * WS + kb0]));
                ldsm_x4(al, s2u(&sHl[lrow * WS + kb0]));
                ldsm_x4(wh, s2u(&sW1h[(jp * 16 + lrow) * WS + kb0]));
                ldsm_x4(wl, s2u(&sW1l[(jp * 16 + lrow) * WS + kb0]));
                #pragma unroll
                for (int jj = 0; jj < 2; ++jj) {
                    unsigned bh[2] = { wh[jj], wh[jj + 2] };
                    unsigned bl_[2] = { wl[jj], wl[jj + 2] };
                    mma16816(acc[jj], ah, bh);
                    mma16816(acc[jj], ah, bl_);
                    mma16816(acc[jj], al, bh);
                }
            }
            #pragma unroll
            for (int jj = 0; jj < 2; ++jj)
                *(float4*)&red[((ks * 4 + jp * 2 + jj) * 32 + lane) * 4] =
                    *(float4*)acc[jj];
        }
        __syncthreads();

        // ---- Phase 1 epilogue: r,z; rh written pre-split ----
        {
            float s = 0.f;
            #pragma unroll
            for (int ks = 0; ks < 8; ++ks)
                s += red[((ks * 4 + jt1) * 32 + lf1) * 4 + cc1];
            float pre = s + pre1v;
            float sg  = __fdividef(1.f, 1.f + __expf(-pre));
            if (jg1 < 16) {
                float rhv = sg * hv;
                __nv_bfloat16 hi, lo;
                split1(rhv, hi, lo);
                g_rhh[b1o * HC + j1] = hi;
                g_rhl[b1o * HC + j1] = lo;
            } else {
                g_z[b1o * HC + (j1 - HC)] = sg;
            }
        }

        // ---- publish P1(my half); wait P1(other half) for my P2 tile ----
        flag_set_and_wait(f1_own, f1_watch, sep);

        // ---- stage rh[p2base + bg2*8 .. +8][:]; prefetch z ----
        float zv = 0.f;
        if (p2own) zv = __ldcg(&g_z[b2o * HC + j2]);
        {
            int i8 = tid;                       // 512 uint4 cover 8 rows
            int row = i8 >> 6, c8 = i8 & 63;
            uint4 vh = __ldcg((const uint4*)&g_rhh[(size_t)(p2base + bg2 * 8 + row) * HC + c8 * 8]);
            uint4 vl = __ldcg((const uint4*)&g_rhl[(size_t)(p2base + bg2 * 8 + row) * HC + c8 * 8]);
            *(uint4*)&sHh[row * WS + c8 * 8] = vh;
            *(uint4*)&sHl[row * WS + c8 * 8] = vl;
        }
        __syncthreads();

        // ---- Phase 2 compute (verbatim; rows 8..15 stale/unused) ----
        {
            const int ks = wp >> 1;
            const int jp = wp & 1;
            float acc[2][4];
            #pragma unroll
            for (int jj = 0; jj < 2; ++jj)
                #pragma unroll
                for (int q = 0; q < 4; ++q) acc[jj][q] = 0.f;
            #pragma unroll
            for (int cc = 0; cc < 4; ++cc) {
                int kb0 = ks * 64 + cc * 16 + lkof;
                unsigned ah[4], al[4], wh[4], wl[4];
                ldsm_x4(ah, s2u(&sHh[lrow * WS + kb0]));
                ldsm_x4(al, s2u(&sHl[lrow * WS + kb0]));
                ldsm_x4(wh, s2u(&sW2h[(jp * 16 + lrow) * WS + kb0]));
                ldsm_x4(wl, s2u(&sW2l[(jp * 16 + lrow) * WS + kb0]));
                #pragma unroll
                for (int jj = 0; jj < 2; ++jj) {
                    unsigned bh[2] = { wh[jj], wh[jj + 2] };
                    unsigned bl_[2] = { wl[jj], wl[jj + 2] };
                    mma16816(acc[jj], ah, bh);
                    mma16816(acc[jj], ah, bl_);
                    mma16816(acc[jj], al, bh);
                }
            }
            #pragma unroll
            for (int jj = 0; jj < 2; ++jj)
                *(float4*)&red[((ks * 4 + jp * 2 + jj) * 32 + lane) * 4] =
                    *(float4*)acc[jj];
        }
        __syncthreads();

        // ---- Phase 2 epilogue: h update, written fp32 + pre-split ----
        if (p2own) {
            float s = 0.f;
            #pragma unroll
            for (int ks = 0; ks < 8; ++ks)
                s += red[((ks * 4 + jt2) * 32 + lf2) * 4 + cc2];
            float x2v = s + pre2v;
            float gg  = 1.f - __fdividef(2.f, __expf(2.f * x2v) + 1.f);
            float hn  = zv * hov + (1.f - zv) * gg;
            g_h[b2o * HC + j2] = hn;
            __nv_bfloat16 hi, lo;
            split1(hn, hi, lo);
            g_hh[b2o * HC + j2] = hi;
            g_hl[b2o * HC + j2] = lo;
            lout[((size_t)t * B_DIM + b2o) * HC + j2] = hn;
            if (t == T_DIM - 1)
                out[OUT_ACT + (size_t)l * B_DIM * HC + b2o * HC + j2] = hn;
        }

        // ---- publish h(t) of my P2 half ----
        flag_set_and_wait(f2_own, nullptr, sep);
    }
}

extern "C" void kernel_launch(void* const* d_in, const int* in_sizes, int n_in,
                              void* d_out, int out_size) {
    const float* x       = (const float*)d_in[0];
    const float* hiddens = (const float*)d_in[1];
    const float* W1      = (const float*)d_in[2];
    const float* b1      = (const float*)d_in[3];
    const float* W2      = (const float*)d_in[4];
    const float* b2      = (const float*)d_in[5];
    float* out = (float*)d_out;

    cudaFuncSetAttribute(serial_kernel,
                         cudaFuncAttributeMaxDynamicSharedMemorySize,
                         SER_SMEM_BYTES);

    for (int l = 0; l < L_DIM; ++l) {
        conv_act<<<M_ALL * IC / 4 / 256, 256>>>(x, l);
        conv_w  <<<N_ALL * IC / 4 / 256, 256>>>(W1, W2, l);
        mma_hoist<<<dim3(24, M_ALL / MBM), 256>>>(b1, b2, l);
        serial_kernel<<<NB, NT, SER_SMEM_BYTES>>>(hiddens, W1, W2, out, l);
    }
}